// round 13
// baseline (speedup 1.0000x reference)
#include <cuda_runtime.h>
#include <cuda_bf16.h>
#include <math.h>
#include <stdint.h>

#define L    512
#define T    96
#define CIN  150
#define HID  150
#define J3   450
#define J3P  480
#define KW   5

// padded GEMM geometry (flat sliding-window im2col)
#define CPAD   152            // padded channel stride (150 + 2)
#define KPAD   768            // 5*152 = 760 -> pad to 768 = 12 chunks of 64
#define KC     64
#define NKC    12
#define RPAD   520
#define NB     512            // xi B padded N

// ---------------- scratch ----------------
__device__ float g_xi [(size_t)T * L * J3P];
__device__ volatile unsigned g_sync[8];
// xtp doubles as the h-history for the recurrent pass: slice t holds
// h_t (layer's hidden state after step t) in padded bf16 hi/lo form.
__device__ __align__(256) __nv_bfloat16 g_xtp_hi[(size_t)T * RPAD * CPAD];
__device__ __align__(256) __nv_bfloat16 g_xtp_lo[(size_t)T * RPAD * CPAD];
__device__ __align__(256) __nv_bfloat16 g_B_hi[(size_t)NB * KPAD];
__device__ __align__(256) __nv_bfloat16 g_B_lo[(size_t)NB * KPAD];
__device__ __align__(256) __nv_bfloat16 g_Br_hi[480 * KPAD];
__device__ __align__(256) __nv_bfloat16 g_Br_lo[480 * KPAD];

extern __shared__ float smem[];

// ---------------- PTX helpers (baseline ISA only) ----------------
__device__ __forceinline__ uint32_t smem_u32(const void* p) {
    uint32_t a;
    asm("{ .reg .u64 t; cvta.to.shared.u64 t, %1; cvt.u32.u64 %0, t; }" : "=r"(a) : "l"(p));
    return a;
}
#define CP_ASYNC16(dst, src) \
    asm volatile("cp.async.cg.shared.global [%0], [%1], 16;" :: "r"(dst), "l"(src))
#define CP_ASYNC8(dst, src) \
    asm volatile("cp.async.ca.shared.global [%0], [%1], 8;" :: "r"(dst), "l"(src))
#define CP_COMMIT() asm volatile("cp.async.commit_group;")
#define CP_WAIT1()  asm volatile("cp.async.wait_group 1;")
#define CP_WAIT0()  asm volatile("cp.async.wait_group 0;")
#define LDSM_X4(r0,r1,r2,r3,a) \
    asm volatile("ldmatrix.sync.aligned.m8n8.x4.shared.b16 {%0,%1,%2,%3}, [%4];" \
        : "=r"(r0),"=r"(r1),"=r"(r2),"=r"(r3) : "r"(a))
#define MMA16816(d,a0,a1,a2,a3,b0,b1) \
    asm volatile("mma.sync.aligned.m16n8k16.row.col.f32.bf16.bf16.f32 " \
        "{%0,%1,%2,%3},{%4,%5,%6,%7},{%8,%9},{%0,%1,%2,%3};" \
        : "+f"((d)[0]),"+f"((d)[1]),"+f"((d)[2]),"+f"((d)[3]) \
        : "r"(a0),"r"(a1),"r"(a2),"r"(a3),"r"(b0),"r"(b1))

__device__ __forceinline__ void signal_release(unsigned* addr) {
    asm volatile("red.release.gpu.global.add.u32 [%0], %1;"
                 :: "l"(addr), "r"(1u) : "memory");
}
__device__ __forceinline__ unsigned ld_acquire(const unsigned* addr) {
    unsigned v;
    asm volatile("ld.acquire.gpu.global.u32 %0, [%1];"
                 : "=r"(v) : "l"(addr) : "memory");
    return v;
}

__device__ __forceinline__ float sigf(float x) {
    float e = __expf(-x);
    return __fdividef(1.f, 1.f + e);
}
__device__ __forceinline__ float tanhfast(float x) {
    return 2.f * sigf(2.f * x) - 1.f;
}

// =====================================================================
// prep kernels
// =====================================================================
__global__ void prep_x_kernel(const float* __restrict__ x) {
    size_t i = (size_t)blockIdx.x * blockDim.x + threadIdx.x;
    const size_t Ntot = (size_t)T * RPAD * CPAD;
    if (i >= Ntot) return;
    int c = i % CPAD;
    int r = (i / CPAD) % RPAD;
    int t = i / ((size_t)CPAD * RPAD);
    float v = 0.f;
    if (r >= 2 && r < 2 + L && c < CIN)
        v = x[(((size_t)(r - 2)) * T + t) * CIN + c];
    __nv_bfloat16 hi = __float2bfloat16(v);
    __nv_bfloat16 lo = __float2bfloat16(v - __bfloat162float(hi));
    g_xtp_hi[i] = hi;
    g_xtp_lo[i] = lo;
}

// combined weight prep: n < NB -> xi weights; else recurrent weights.
// Also zeroes g_sync (block 0).
__global__ void prep_wb_kernel(const float* __restrict__ Wi,
                               const float* __restrict__ Wh) {
    if (blockIdx.x == 0 && threadIdx.x < 8) g_sync[threadIdx.x] = 0u;
    size_t i = (size_t)blockIdx.x * blockDim.x + threadIdx.x;
    const size_t Ntot = (size_t)(NB + 480) * KPAD;
    if (i >= Ntot) return;
    int k = i % KPAD;
    int n = i / KPAD;
    int tap = k / CPAD, c = k % CPAD;
    float v = 0.f;
    if (n < NB) {
        if (n < J3 && tap < KW && c < CIN)
            v = Wi[((size_t)tap * CIN + c) * J3 + n];
        __nv_bfloat16 hi = __float2bfloat16(v);
        __nv_bfloat16 lo = __float2bfloat16(v - __bfloat162float(hi));
        g_B_hi[(size_t)n * KPAD + k] = hi;
        g_B_lo[(size_t)n * KPAD + k] = lo;
    } else {
        int n2 = n - NB;
        int cg = n2 >> 5, j = n2 & 31;
        if (j < 30 && tap < KW && c < CIN) {
            int gate = j / 10, ch = j - gate * 10;
            v = Wh[((size_t)tap * CIN + c) * J3 + gate * HID + cg * 10 + ch];
        }
        __nv_bfloat16 hi = __float2bfloat16(v);
        __nv_bfloat16 lo = __float2bfloat16(v - __bfloat162float(hi));
        g_Br_hi[(size_t)n2 * KPAD + k] = hi;
        g_Br_lo[(size_t)n2 * KPAD + k] = lo;
    }
}

// =====================================================================
// xi via mma.sync bf16 split, v3: 3-stage cp.async pipeline, ONE
// syncthreads per K-chunk. grid (96,4,4), 512 thr (16 warps, 4mw x 4nw,
// warp tile 32x32). smem = 3 x 64KB buffers.
// Per iter kc: WAIT(group kc) -> sync -> issue stage(kc+2) (overwrites
// the buffer last read at kc-1, protected by the sync) -> MMA(kc).
// =====================================================================
#define BUFSZ 65536
#define SM_XI_TOTAL (3 * BUFSZ)

__global__ __launch_bounds__(512, 1) void xi_mma_kernel(
    const float* __restrict__ bi, float* __restrict__ xi)
{
    char* sm = reinterpret_cast<char*>(smem);
    const uint32_t smb = smem_u32(sm);
    const int tid = threadIdx.x;
    const int lane = tid & 31, wid = tid >> 5;
    const int t = blockIdx.x, mblk = blockIdx.y, nblk = blockIdx.z;

    const int mw = wid & 3, nw = wid >> 2;   // 4 x 4 warps
    const int m0 = mw * 32, n0 = nw * 32;

    int aRow[2], aXor[2];
    const int jA = (lane >> 4) & 1;
    #pragma unroll
    for (int mt = 0; mt < 2; mt++) {
        aRow[mt] = (m0 + mt * 16 + (lane & 15)) * 128;
        aXor[mt] = ((m0 + mt * 16 + (lane & 15)) & 7);
    }
    int bRow[2], bXor[2];
    const int jB = (lane >> 3) & 1;
    #pragma unroll
    for (int np = 0; np < 2; np++) {
        int r = n0 + np * 16 + (lane & 7) + ((lane >> 4) & 1) * 8;
        bRow[np] = r * 128;
        bXor[np] = r & 7;
    }

    const __nv_bfloat16* srcA_hi = g_xtp_hi + ((size_t)t * RPAD + (size_t)mblk * 128) * CPAD;
    const __nv_bfloat16* srcA_lo = g_xtp_lo + ((size_t)t * RPAD + (size_t)mblk * 128) * CPAD;
    const __nv_bfloat16* srcB_hi = g_B_hi + (size_t)nblk * 128 * KPAD;
    const __nv_bfloat16* srcB_lo = g_B_lo + (size_t)nblk * 128 * KPAD;

    float acc[2][4][4];
    #pragma unroll
    for (int mt = 0; mt < 2; mt++)
        #pragma unroll
        for (int nt = 0; nt < 4; nt++)
            #pragma unroll
            for (int k = 0; k < 4; k++) acc[mt][nt][k] = 0.f;

    auto stage = [&](int kc, int buf) {
        const uint32_t base = smb + buf * BUFSZ;
        #pragma unroll
        for (int it = 0; it < 8; it++) {
            int u = it * 512 + tid;
            int arr = u >> 10;
            int v = u & 1023;
            int row = v >> 3, seg = v & 7;
            const __nv_bfloat16* src;
            if (arr == 0)      src = srcA_hi + (size_t)row * CPAD + kc * KC + seg * 8;
            else if (arr == 1) src = srcA_lo + (size_t)row * CPAD + kc * KC + seg * 8;
            else if (arr == 2) src = srcB_hi + (size_t)row * KPAD + kc * KC + seg * 8;
            else               src = srcB_lo + (size_t)row * KPAD + kc * KC + seg * 8;
            uint32_t dst = base + arr * 16384 + row * 128 + ((seg ^ (row & 7)) << 4);
            CP_ASYNC16(dst, src);
        }
    };

    stage(0, 0); CP_COMMIT();
    stage(1, 1); CP_COMMIT();

    #pragma unroll
    for (int kc = 0; kc < NKC; kc++) {
        if (kc < NKC - 1) { CP_WAIT1(); } else { CP_WAIT0(); }
        __syncthreads();
        if (kc + 2 < NKC) {
            stage(kc + 2, (kc + 2) % 3);
            CP_COMMIT();
        }

        const uint32_t bA_hi = smb + (kc % 3) * BUFSZ;
        const uint32_t bA_lo = bA_hi + 16384;
        const uint32_t bB_hi = bA_hi + 32768;
        const uint32_t bB_lo = bA_hi + 49152;

        #pragma unroll
        for (int ks = 0; ks < 4; ks++) {
            uint32_t ah[2][4], al[2][4];
            #pragma unroll
            for (int mt = 0; mt < 2; mt++) {
                uint32_t off = aRow[mt] + (((2 * ks + jA) ^ aXor[mt]) << 4);
                LDSM_X4(ah[mt][0], ah[mt][1], ah[mt][2], ah[mt][3], bA_hi + off);
                LDSM_X4(al[mt][0], al[mt][1], al[mt][2], al[mt][3], bA_lo + off);
            }
            #pragma unroll
            for (int np = 0; np < 2; np++) {
                // skip tiles entirely in the N-padding (never stored)
                if (nblk * 128 + n0 + np * 16 >= J3) continue;
                uint32_t off = bRow[np] + (((2 * ks + jB) ^ bXor[np]) << 4);
                uint32_t bh[4], bl[4];
                LDSM_X4(bh[0], bh[1], bh[2], bh[3], bB_hi + off);
                LDSM_X4(bl[0], bl[1], bl[2], bl[3], bB_lo + off);
                #pragma unroll
                for (int mt = 0; mt < 2; mt++) {
                    float* d0 = acc[mt][np * 2];
                    float* d1 = acc[mt][np * 2 + 1];
                    MMA16816(d0, ah[mt][0], ah[mt][1], ah[mt][2], ah[mt][3], bh[0], bh[1]);
                    MMA16816(d0, al[mt][0], al[mt][1], al[mt][2], al[mt][3], bh[0], bh[1]);
                    MMA16816(d0, ah[mt][0], ah[mt][1], ah[mt][2], ah[mt][3], bl[0], bl[1]);
                    MMA16816(d1, ah[mt][0], ah[mt][1], ah[mt][2], ah[mt][3], bh[2], bh[3]);
                    MMA16816(d1, al[mt][0], al[mt][1], al[mt][2], al[mt][3], bh[2], bh[3]);
                    MMA16816(d1, ah[mt][0], ah[mt][1], ah[mt][2], ah[mt][3], bl[2], bl[3]);
                }
            }
        }
    }

    const int g  = lane >> 2;
    const int tq = lane & 3;
    #pragma unroll
    for (int mt = 0; mt < 2; mt++) {
        int r0 = mblk * 128 + m0 + mt * 16 + g;
        int r1 = r0 + 8;
        float* row0 = xi + ((size_t)t * L + r0) * J3P;
        float* row1 = xi + ((size_t)t * L + r1) * J3P;
        #pragma unroll
        for (int nt = 0; nt < 4; nt++) {
            int j0 = nblk * 128 + n0 + nt * 8 + tq * 2;
            if (j0 < J3) {
                float b0 = bi[j0], b1 = bi[j0 + 1];
                float2 v0 = make_float2(acc[mt][nt][0] + b0, acc[mt][nt][1] + b1);
                float2 v1 = make_float2(acc[mt][nt][2] + b0, acc[mt][nt][3] + b1);
                *reinterpret_cast<float2*>(row0 + j0) = v0;
                *reinterpret_cast<float2*>(row1 + j0) = v1;
            }
        }
    }
}

// =====================================================================
// Persistent recurrent MMA kernel, v7: release/acquire sync.
// grid (15 cg, 8 mg) = 120 blocks, 512 thr = 16 warps as 4mw x 4kw.
// Changes vs v6:
//  - completion signal: __syncthreads() then tid0 red.release.gpu
//    (replaces __threadfence + relaxed atomicAdd) — the canonical
//    grid-barrier release pattern.
//  - ALL threads poll with ld.acquire.gpu (3 counters each); the
//    post-poll __syncthreads is gone — warps start staging as soon as
//    they observe the release.
// =====================================================================
#define SM_RB_HI 0
#define SM_RB_LO 49152
#define SM_RA    98304
#define HALO_B   20736          // 68*304 = 20672, rounded up to 128
#define SM_RHH   (SM_RA + 2 * HALO_B)          // 139776 (4 x 8192)
#define SM_XI    (SM_RHH + 32768)              // 172544
#define SM_REC_TOTAL (SM_XI + 8192)            // 180736

__global__ __launch_bounds__(512, 1) void rec_mma_kernel(
    const float* __restrict__ xi, float* __restrict__ outp, int layer)
{
    char* sm = reinterpret_cast<char*>(smem);
    const uint32_t smb = smem_u32(sm);
    float* sh_hh0 = reinterpret_cast<float*>(sm + SM_RHH);
    float* sh_hh1 = reinterpret_cast<float*>(sm + SM_RHH + 8192);
    float* sh_hh2 = reinterpret_cast<float*>(sm + SM_RHH + 16384);
    float* sh_hh3 = reinterpret_cast<float*>(sm + SM_RHH + 24576);
    float* sh_xi  = reinterpret_cast<float*>(sm + SM_XI);
    const int tid = threadIdx.x;
    const int lane = tid & 31, wid = tid >> 5;
    const int cg = blockIdx.x, mg = blockIdx.y;
    const int c0 = cg * 10;
    const int l0 = mg * 64;
    const int mglo = (mg > 0) ? mg - 1 : 0;
    const int mghi = (mg < 7) ? mg + 1 : 7;

    const int mw = wid & 3;             // 4 m-warps (16 rows each)
    const int kw = wid >> 2;            // 4 K-split groups (3 kc each)
    const int m0w = mw * 16;
    float* sh_hh_my = (kw == 0) ? sh_hh0 : (kw == 1) ? sh_hh1
                     : (kw == 2) ? sh_hh2 : sh_hh3;

    // A lane offset into compact halo (row stride 304B, k-half select jA)
    const int jA = (lane >> 4) & 1;
    const uint32_t aLane = (uint32_t)(m0w + (lane & 15)) * 304 + jA * 16;
    // B lane addressing (swizzled resident buffer), two n16 groups
    const int bR = (lane & 7) + ((lane >> 4) & 1) * 8;   // rows 0..15
    const int bRowOff0 = bR * 128;
    const int bRowOff1 = (bR + 16) * 128;                // (bR+16)&7 == bR&7
    const int bXor = bR & 7;
    const int jB = (lane >> 3) & 1;

    // ---- zero-init the entire halo region ONCE (t=0 state + K-pad tail) ----
    {
        uint4 z = make_uint4(0, 0, 0, 0);
        for (int u = tid; u < (2 * HALO_B) / 16; u += 512)
            *reinterpret_cast<uint4*>(sm + SM_RA + u * 16) = z;
    }

    // ---- load resident B (weights) once: 2 arr x 12 chunks x 32 rows x 8 segs ----
    for (int u = tid; u < 6144; u += 512) {
        int arr = u / 3072;
        int v = u - arr * 3072;
        int chunk = v >> 8;
        int w = v & 255;
        int row = w >> 3, seg = w & 7;
        const __nv_bfloat16* src =
            (arr ? g_Br_lo : g_Br_hi) + ((size_t)(cg * 32 + row)) * KPAD + chunk * KC + seg * 8;
        uint32_t dst = smb + (arr ? SM_RB_LO : SM_RB_HI)
                     + chunk * 4096 + row * 128 + ((seg ^ (row & 7)) << 4);
        CP_ASYNC16(dst, src);
    }
    CP_COMMIT();
    CP_WAIT0();
    __syncthreads();

    for (int t = 0; t < T; t++) {
        // neighbor sync: ALL threads poll mg-1, mg, mg+1 with acquire loads.
        // No syncthreads needed after: each thread's staging reads are
        // ordered after its own acquires; the pre-MMA barrier re-converges.
        if (t > 0) {
            const unsigned tgt = 15u * (unsigned)t;
            for (int m = mglo; m <= mghi; m++)
                while (ld_acquire((const unsigned*)&g_sync[m]) < tgt) { }
        }

        // ---- stage compact halo from xtp[t-1] (group 0, gated before MMA) ----
        if (t > 0) {
            const __nv_bfloat16* baseHi = g_xtp_hi + ((size_t)(t - 1) * RPAD + l0) * CPAD;
            const __nv_bfloat16* baseLo = g_xtp_lo + ((size_t)(t - 1) * RPAD + l0) * CPAD;
            for (int u = tid; u < 2584; u += 512) {
                int arr = u >= 1292;
                int v = arr ? u - 1292 : u;
                const __nv_bfloat16* src = (arr ? baseLo : baseHi) + v * 8;
                uint32_t dst = smb + SM_RA + arr * HALO_B + v * 16;
                CP_ASYNC16(dst, src);
            }
            CP_COMMIT();
        }
        // ---- prefetch xi gate slice (group 1, only needed at epilogue) ----
        {
            const float* xibase = xi + ((size_t)t * L + l0) * J3P + c0;
            for (int u = tid; u < 960; u += 512) {
                int lr = u / 15, rem = u - lr * 15;
                int gate = rem / 5, seg = rem - gate * 5;
                const float* src = xibase + (size_t)lr * J3P + gate * HID + seg * 2;
                uint32_t dst = smb + SM_XI + lr * 128 + gate * 40 + seg * 8;
                CP_ASYNC8(dst, src);
            }
            CP_COMMIT();
        }
        if (t > 0) CP_WAIT1();   // halo complete; xi may still be in flight
        __syncthreads();

        float a0[4][4];   // 4 n8-tiles x 4 regs
        #pragma unroll
        for (int nt = 0; nt < 4; nt++)
            #pragma unroll
            for (int k = 0; k < 4; k++) a0[nt][k] = 0.f;

        const uint32_t aHi = smb + SM_RA + aLane;
        const uint32_t aLo = aHi + HALO_B;
        const int kcBeg = kw * 3;

        #pragma unroll
        for (int kc2 = 0; kc2 < 3; kc2++) {
            const int kc = kcBeg + kc2;
            const uint32_t bBh = smb + SM_RB_HI + kc * 4096;
            const uint32_t bBl = smb + SM_RB_LO + kc * 4096;
            #pragma unroll
            for (int ks = 0; ks < 4; ks++) {
                uint32_t aoff = kc * 128 + ks * 32;
                uint32_t ah[4], al[4];
                LDSM_X4(ah[0], ah[1], ah[2], ah[3], aHi + aoff);
                LDSM_X4(al[0], al[1], al[2], al[3], aLo + aoff);
                uint32_t bko = (((2 * ks + jB) ^ bXor) << 4);
                uint32_t bh[8], bl[8];
                LDSM_X4(bh[0], bh[1], bh[2], bh[3], bBh + bRowOff0 + bko);
                LDSM_X4(bh[4], bh[5], bh[6], bh[7], bBh + bRowOff1 + bko);
                LDSM_X4(bl[0], bl[1], bl[2], bl[3], bBl + bRowOff0 + bko);
                LDSM_X4(bl[4], bl[5], bl[6], bl[7], bBl + bRowOff1 + bko);
                #pragma unroll
                for (int j = 0; j < 4; j++) {
                    float* d = a0[j];
                    MMA16816(d, ah[0], ah[1], ah[2], ah[3], bh[2 * j], bh[2 * j + 1]);
                    MMA16816(d, al[0], al[1], al[2], al[3], bh[2 * j], bh[2 * j + 1]);
                    MMA16816(d, ah[0], ah[1], ah[2], ah[3], bl[2 * j], bl[2 * j + 1]);
                }
            }
        }

        // ---- stage hh partials into this K-group's smem buffer ----
        {
            const int g = lane >> 2, tq = lane & 3;
            int r0 = m0w + g;
            int r1 = r0 + 8;
            #pragma unroll
            for (int j = 0; j < 4; j++) {
                int col = j * 8 + tq * 2;
                sh_hh_my[r0 * 32 + col]     = a0[j][0];
                sh_hh_my[r0 * 32 + col + 1] = a0[j][1];
                sh_hh_my[r1 * 32 + col]     = a0[j][2];
                sh_hh_my[r1 * 32 + col + 1] = a0[j][3];
            }
        }
        CP_WAIT0();       // xi slice now resident
        __syncthreads();

        // ---- gate epilogue: 64 rows x 10 channels, all smem-sourced ----
        {
            for (int e = tid; e < 640; e += 512) {
                int lr = e / 10, ch = e - lr * 10;
                int l = l0 + lr, c = c0 + ch;
                int b = lr * 32;
                float hr = sh_hh0[b + ch]      + sh_hh1[b + ch]
                         + sh_hh2[b + ch]      + sh_hh3[b + ch];
                float hz = sh_hh0[b + 10 + ch] + sh_hh1[b + 10 + ch]
                         + sh_hh2[b + 10 + ch] + sh_hh3[b + 10 + ch];
                float hn = sh_hh0[b + 20 + ch] + sh_hh1[b + 20 + ch]
                         + sh_hh2[b + 20 + ch] + sh_hh3[b + 20 + ch];
                const float* qx = sh_xi + lr * 32;
                float xr = qx[ch], xz = qx[10 + ch], xn = qx[20 + ch];
                // h_prev reconstructed from the staged halo (hi+lo)
                uint32_t hoff = (uint32_t)(lr + 2) * 304 + 2u * (uint32_t)c;
                float hpv =
                    __bfloat162float(*reinterpret_cast<__nv_bfloat16*>(sm + SM_RA + hoff)) +
                    __bfloat162float(*reinterpret_cast<__nv_bfloat16*>(sm + SM_RA + HALO_B + hoff));
                float r = sigf(xr + hr);
                float z = sigf(xz + hz);
                float n = tanhfast(xn + r * hn);
                float hnew = n + z * (hpv - n);

                __nv_bfloat16 hi = __float2bfloat16(hnew);
                __nv_bfloat16 lo = __float2bfloat16(hnew - __bfloat162float(hi));
                size_t xidx = ((size_t)t * RPAD + (l + 2)) * CPAD + c;
                g_xtp_hi[xidx] = hi;
                g_xtp_lo[xidx] = lo;
                if (layer == 1)
                    outp[((size_t)l * T + t) * HID + c] = hnew;
            }
        }

        // signal completion of step t: block barrier then release-reduction
        // (bar.sync makes the block's stores A-cumulative under the release)
        __syncthreads();
        if (tid == 0) signal_release((unsigned*)&g_sync[mg]);
    }
}

// =====================================================================
extern "C" void kernel_launch(void* const* d_in, const int* in_sizes, int n_in,
                              void* d_out, int out_size)
{
    (void)in_sizes; (void)n_in; (void)out_size;
    const float* xs  = (const float*)d_in[0];
    const float* Wi0 = (const float*)d_in[1];
    const float* bi0 = (const float*)d_in[2];
    const float* Wh0 = (const float*)d_in[3];
    const float* Wi1 = (const float*)d_in[4];
    const float* bi1 = (const float*)d_in[5];
    const float* Wh1 = (const float*)d_in[6];
    float* out = (float*)d_out;

    float* xi;
    cudaGetSymbolAddress((void**)&xi, g_xi);

    static int attr_done = 0;
    if (!attr_done) {
        cudaFuncSetAttribute(xi_mma_kernel, cudaFuncAttributeMaxDynamicSharedMemorySize, SM_XI_TOTAL);
        cudaFuncSetAttribute(rec_mma_kernel, cudaFuncAttributeMaxDynamicSharedMemorySize, SM_REC_TOTAL);
        attr_done = 1;
    }

    const size_t n_prep_x = (size_t)T * RPAD * CPAD;
    const int    gx = (int)((n_prep_x + 255) / 256);
    const size_t n_prep_wb = (size_t)(NB + 480) * KPAD;
    const int    gwb = (int)((n_prep_wb + 255) / 256);
    const dim3 grid_mma(T, 4, 4);
    const dim3 grid_rec(15, 8);

    for (int layer = 0; layer < 2; layer++) {
        const float* Wi = layer ? Wi1 : Wi0;
        const float* bi = layer ? bi1 : bi0;
        const float* Wh = layer ? Wh1 : Wh0;

        if (layer == 0) prep_x_kernel<<<gx, 256>>>(xs);
        prep_wb_kernel<<<gwb, 256>>>(Wi, Wh);
        xi_mma_kernel<<<grid_mma, 512, SM_XI_TOTAL>>>(bi, xi);
        rec_mma_kernel<<<grid_rec, 512, SM_REC_TOTAL>>>(xi, out, layer);
    }
}

// round 14
// speedup vs baseline: 1.1693x; 1.1693x over previous
#include <cuda_runtime.h>
#include <cuda_bf16.h>
#include <math.h>
#include <stdint.h>

#define L    512
#define T    96
#define CIN  150
#define HID  150
#define J3   450
#define J3P  480
#define KW   5

// padded GEMM geometry (flat sliding-window im2col)
#define CPAD   152            // padded channel stride (150 + 2)
#define KPAD   768            // 5*152 = 760 -> pad to 768 = 12 chunks of 64
#define KC     64
#define NKC    12
#define RPAD   520
#define NB     512            // xi B padded N

// ---------------- scratch ----------------
__device__ float g_xi [(size_t)T * L * J3P];
__device__ volatile unsigned g_sync[8];
// xtp doubles as the h-history for the recurrent pass: slice t holds
// h_t (layer's hidden state after step t) in padded bf16 hi/lo form.
__device__ __align__(256) __nv_bfloat16 g_xtp_hi[(size_t)T * RPAD * CPAD];
__device__ __align__(256) __nv_bfloat16 g_xtp_lo[(size_t)T * RPAD * CPAD];
__device__ __align__(256) __nv_bfloat16 g_B_hi[(size_t)NB * KPAD];
__device__ __align__(256) __nv_bfloat16 g_B_lo[(size_t)NB * KPAD];
__device__ __align__(256) __nv_bfloat16 g_Br_hi[480 * KPAD];
__device__ __align__(256) __nv_bfloat16 g_Br_lo[480 * KPAD];

extern __shared__ float smem[];

// ---------------- PTX helpers (baseline ISA only) ----------------
__device__ __forceinline__ uint32_t smem_u32(const void* p) {
    uint32_t a;
    asm("{ .reg .u64 t; cvta.to.shared.u64 t, %1; cvt.u32.u64 %0, t; }" : "=r"(a) : "l"(p));
    return a;
}
#define CP_ASYNC16(dst, src) \
    asm volatile("cp.async.cg.shared.global [%0], [%1], 16;" :: "r"(dst), "l"(src))
#define CP_ASYNC8(dst, src) \
    asm volatile("cp.async.ca.shared.global [%0], [%1], 8;" :: "r"(dst), "l"(src))
#define CP_COMMIT() asm volatile("cp.async.commit_group;")
#define CP_WAIT1()  asm volatile("cp.async.wait_group 1;")
#define CP_WAIT0()  asm volatile("cp.async.wait_group 0;")
#define LDSM_X4(r0,r1,r2,r3,a) \
    asm volatile("ldmatrix.sync.aligned.m8n8.x4.shared.b16 {%0,%1,%2,%3}, [%4];" \
        : "=r"(r0),"=r"(r1),"=r"(r2),"=r"(r3) : "r"(a))
#define MMA16816(d,a0,a1,a2,a3,b0,b1) \
    asm volatile("mma.sync.aligned.m16n8k16.row.col.f32.bf16.bf16.f32 " \
        "{%0,%1,%2,%3},{%4,%5,%6,%7},{%8,%9},{%0,%1,%2,%3};" \
        : "+f"((d)[0]),"+f"((d)[1]),"+f"((d)[2]),"+f"((d)[3]) \
        : "r"(a0),"r"(a1),"r"(a2),"r"(a3),"r"(b0),"r"(b1))

__device__ __forceinline__ float sigf(float x) {
    float e = __expf(-x);
    return __fdividef(1.f, 1.f + e);
}
__device__ __forceinline__ float tanhfast(float x) {
    return 2.f * sigf(2.f * x) - 1.f;
}

// =====================================================================
// prep kernels (unchanged from R12)
// =====================================================================
__global__ void prep_x_kernel(const float* __restrict__ x) {
    size_t i = (size_t)blockIdx.x * blockDim.x + threadIdx.x;
    const size_t Ntot = (size_t)T * RPAD * CPAD;
    if (i >= Ntot) return;
    int c = i % CPAD;
    int r = (i / CPAD) % RPAD;
    int t = i / ((size_t)CPAD * RPAD);
    float v = 0.f;
    if (r >= 2 && r < 2 + L && c < CIN)
        v = x[(((size_t)(r - 2)) * T + t) * CIN + c];
    __nv_bfloat16 hi = __float2bfloat16(v);
    __nv_bfloat16 lo = __float2bfloat16(v - __bfloat162float(hi));
    g_xtp_hi[i] = hi;
    g_xtp_lo[i] = lo;
}

__global__ void prep_wb_kernel(const float* __restrict__ Wi,
                               const float* __restrict__ Wh) {
    if (blockIdx.x == 0 && threadIdx.x < 8) g_sync[threadIdx.x] = 0u;
    size_t i = (size_t)blockIdx.x * blockDim.x + threadIdx.x;
    const size_t Ntot = (size_t)(NB + 480) * KPAD;
    if (i >= Ntot) return;
    int k = i % KPAD;
    int n = i / KPAD;
    int tap = k / CPAD, c = k % CPAD;
    float v = 0.f;
    if (n < NB) {
        if (n < J3 && tap < KW && c < CIN)
            v = Wi[((size_t)tap * CIN + c) * J3 + n];
        __nv_bfloat16 hi = __float2bfloat16(v);
        __nv_bfloat16 lo = __float2bfloat16(v - __bfloat162float(hi));
        g_B_hi[(size_t)n * KPAD + k] = hi;
        g_B_lo[(size_t)n * KPAD + k] = lo;
    } else {
        int n2 = n - NB;
        int cg = n2 >> 5, j = n2 & 31;
        if (j < 30 && tap < KW && c < CIN) {
            int gate = j / 10, ch = j - gate * 10;
            v = Wh[((size_t)tap * CIN + c) * J3 + gate * HID + cg * 10 + ch];
        }
        __nv_bfloat16 hi = __float2bfloat16(v);
        __nv_bfloat16 lo = __float2bfloat16(v - __bfloat162float(hi));
        g_Br_hi[(size_t)n2 * KPAD + k] = hi;
        g_Br_lo[(size_t)n2 * KPAD + k] = lo;
    }
}

// =====================================================================
// xi via mma.sync bf16 split (R12-proven): grid (96,4,4), 512 thr,
// 2-buffer cp.async double-buffering, warp tile 32x32 (4mw x 4nw).
// =====================================================================
#define BUFSZ 65536

__global__ __launch_bounds__(512, 1) void xi_mma_kernel(
    const float* __restrict__ bi, float* __restrict__ xi)
{
    char* sm = reinterpret_cast<char*>(smem);
    const uint32_t smb = smem_u32(sm);
    const int tid = threadIdx.x;
    const int lane = tid & 31, wid = tid >> 5;
    const int t = blockIdx.x, mblk = blockIdx.y, nblk = blockIdx.z;

    const int mw = wid & 3, nw = wid >> 2;   // 4 x 4 warps
    const int m0 = mw * 32, n0 = nw * 32;

    int aRow[2], aXor[2];
    const int jA = (lane >> 4) & 1;
    #pragma unroll
    for (int mt = 0; mt < 2; mt++) {
        aRow[mt] = (m0 + mt * 16 + (lane & 15)) * 128;
        aXor[mt] = ((m0 + mt * 16 + (lane & 15)) & 7);
    }
    int bRow[2], bXor[2];
    const int jB = (lane >> 3) & 1;
    #pragma unroll
    for (int np = 0; np < 2; np++) {
        int r = n0 + np * 16 + (lane & 7) + ((lane >> 4) & 1) * 8;
        bRow[np] = r * 128;
        bXor[np] = r & 7;
    }

    const __nv_bfloat16* srcA_hi = g_xtp_hi + ((size_t)t * RPAD + (size_t)mblk * 128) * CPAD;
    const __nv_bfloat16* srcA_lo = g_xtp_lo + ((size_t)t * RPAD + (size_t)mblk * 128) * CPAD;
    const __nv_bfloat16* srcB_hi = g_B_hi + (size_t)nblk * 128 * KPAD;
    const __nv_bfloat16* srcB_lo = g_B_lo + (size_t)nblk * 128 * KPAD;

    float acc[2][4][4];
    #pragma unroll
    for (int mt = 0; mt < 2; mt++)
        #pragma unroll
        for (int nt = 0; nt < 4; nt++)
            #pragma unroll
            for (int k = 0; k < 4; k++) acc[mt][nt][k] = 0.f;

    auto stage = [&](int kc, int buf) {
        const uint32_t base = smb + buf * BUFSZ;
        #pragma unroll
        for (int it = 0; it < 8; it++) {
            int u = it * 512 + tid;
            int arr = u >> 10;
            int v = u & 1023;
            int row = v >> 3, seg = v & 7;
            const __nv_bfloat16* src;
            if (arr == 0)      src = srcA_hi + (size_t)row * CPAD + kc * KC + seg * 8;
            else if (arr == 1) src = srcA_lo + (size_t)row * CPAD + kc * KC + seg * 8;
            else if (arr == 2) src = srcB_hi + (size_t)row * KPAD + kc * KC + seg * 8;
            else               src = srcB_lo + (size_t)row * KPAD + kc * KC + seg * 8;
            uint32_t dst = base + arr * 16384 + row * 128 + ((seg ^ (row & 7)) << 4);
            CP_ASYNC16(dst, src);
        }
    };

    stage(0, 0);
    CP_COMMIT();

    for (int kc = 0; kc < NKC; kc++) {
        const int buf = kc & 1;
        if (kc + 1 < NKC) {
            stage(kc + 1, buf ^ 1);
            CP_COMMIT();
            CP_WAIT1();
        } else {
            CP_WAIT0();
        }
        __syncthreads();

        const uint32_t bA_hi = smb + buf * BUFSZ;
        const uint32_t bA_lo = bA_hi + 16384;
        const uint32_t bB_hi = bA_hi + 32768;
        const uint32_t bB_lo = bA_hi + 49152;

        #pragma unroll
        for (int ks = 0; ks < 4; ks++) {
            uint32_t ah[2][4], al[2][4];
            #pragma unroll
            for (int mt = 0; mt < 2; mt++) {
                uint32_t off = aRow[mt] + (((2 * ks + jA) ^ aXor[mt]) << 4);
                LDSM_X4(ah[mt][0], ah[mt][1], ah[mt][2], ah[mt][3], bA_hi + off);
                LDSM_X4(al[mt][0], al[mt][1], al[mt][2], al[mt][3], bA_lo + off);
            }
            #pragma unroll
            for (int np = 0; np < 2; np++) {
                if (nblk * 128 + n0 + np * 16 >= J3) continue;
                uint32_t off = bRow[np] + (((2 * ks + jB) ^ bXor[np]) << 4);
                uint32_t bh[4], bl[4];
                LDSM_X4(bh[0], bh[1], bh[2], bh[3], bB_hi + off);
                LDSM_X4(bl[0], bl[1], bl[2], bl[3], bB_lo + off);
                #pragma unroll
                for (int mt = 0; mt < 2; mt++) {
                    float* d0 = acc[mt][np * 2];
                    float* d1 = acc[mt][np * 2 + 1];
                    MMA16816(d0, ah[mt][0], ah[mt][1], ah[mt][2], ah[mt][3], bh[0], bh[1]);
                    MMA16816(d0, al[mt][0], al[mt][1], al[mt][2], al[mt][3], bh[0], bh[1]);
                    MMA16816(d0, ah[mt][0], ah[mt][1], ah[mt][2], ah[mt][3], bl[0], bl[1]);
                    MMA16816(d1, ah[mt][0], ah[mt][1], ah[mt][2], ah[mt][3], bh[2], bh[3]);
                    MMA16816(d1, al[mt][0], al[mt][1], al[mt][2], al[mt][3], bh[2], bh[3]);
                    MMA16816(d1, ah[mt][0], ah[mt][1], ah[mt][2], ah[mt][3], bl[2], bl[3]);
                }
            }
        }
        __syncthreads();
    }

    const int g  = lane >> 2;
    const int tq = lane & 3;
    #pragma unroll
    for (int mt = 0; mt < 2; mt++) {
        int r0 = mblk * 128 + m0 + mt * 16 + g;
        int r1 = r0 + 8;
        float* row0 = xi + ((size_t)t * L + r0) * J3P;
        float* row1 = xi + ((size_t)t * L + r1) * J3P;
        #pragma unroll
        for (int nt = 0; nt < 4; nt++) {
            int j0 = nblk * 128 + n0 + nt * 8 + tq * 2;
            if (j0 < J3) {
                float b0 = bi[j0], b1 = bi[j0 + 1];
                float2 v0 = make_float2(acc[mt][nt][0] + b0, acc[mt][nt][1] + b1);
                float2 v1 = make_float2(acc[mt][nt][2] + b0, acc[mt][nt][3] + b1);
                *reinterpret_cast<float2*>(row0 + j0) = v0;
                *reinterpret_cast<float2*>(row1 + j0) = v1;
            }
        }
    }
}

// =====================================================================
// Persistent recurrent MMA kernel, v8: mw=2 x kw=6 warp grid (384 thr).
// LDSM traffic 388KB/step/block (A dup 1, B dup 2; was 580KB in R12).
// Warp tile m32 x n32, 2 K-chunks per warp; 6 partial hh buffers summed
// in the epilogue. Sync = proven R12 scheme (tid<3 volatile poll +
// syncthreads; threadfence + relaxed atomicAdd release).
// =====================================================================
#define RTHR 384
#define SM_RB_HI 0
#define SM_RB_LO 49152
#define SM_RA    98304
#define HALO_B   20736          // 68*304 = 20672, rounded up to 128
#define SM_RHH   (SM_RA + 2 * HALO_B)          // 139776 (6 x 8192)
#define SM_XI    (SM_RHH + 49152)              // 188928
#define SM_REC_TOTAL (SM_XI + 8192)            // 197120

__global__ __launch_bounds__(RTHR, 1) void rec_mma_kernel(
    const float* __restrict__ xi, float* __restrict__ outp, int layer)
{
    char* sm = reinterpret_cast<char*>(smem);
    const uint32_t smb = smem_u32(sm);
    float* sh_xi  = reinterpret_cast<float*>(sm + SM_XI);
    const int tid = threadIdx.x;
    const int lane = tid & 31, wid = tid >> 5;
    const int cg = blockIdx.x, mg = blockIdx.y;
    const int c0 = cg * 10;
    const int l0 = mg * 64;

    const int mw = wid & 1;             // 2 m-warps (32 rows each)
    const int kw = wid >> 1;            // 6 K-split groups (2 kc each)
    const int m0w = mw * 32;
    float* sh_hh_my = reinterpret_cast<float*>(sm + SM_RHH + kw * 8192);

    // A lane offsets into compact halo (row stride 304B); 2 m16 tiles
    const int jA = (lane >> 4) & 1;
    const uint32_t aLane0 = (uint32_t)(m0w + (lane & 15)) * 304 + jA * 16;
    const uint32_t aLane1 = (uint32_t)(m0w + 16 + (lane & 15)) * 304 + jA * 16;
    // B lane addressing (swizzled resident buffer), two n16 groups
    const int bR = (lane & 7) + ((lane >> 4) & 1) * 8;   // rows 0..15
    const int bRowOff0 = bR * 128;
    const int bRowOff1 = (bR + 16) * 128;                // (bR+16)&7 == bR&7
    const int bXor = bR & 7;
    const int jB = (lane >> 3) & 1;

    // ---- zero-init the entire halo region ONCE (t=0 state + K-pad tail) ----
    {
        uint4 z = make_uint4(0, 0, 0, 0);
        for (int u = tid; u < (2 * HALO_B) / 16; u += RTHR)
            *reinterpret_cast<uint4*>(sm + SM_RA + u * 16) = z;
    }

    // ---- load resident B (weights) once: 2 arr x 12 chunks x 32 rows x 8 segs ----
    for (int u = tid; u < 6144; u += RTHR) {
        int arr = u / 3072;
        int v = u - arr * 3072;
        int chunk = v >> 8;
        int w = v & 255;
        int row = w >> 3, seg = w & 7;
        const __nv_bfloat16* src =
            (arr ? g_Br_lo : g_Br_hi) + ((size_t)(cg * 32 + row)) * KPAD + chunk * KC + seg * 8;
        uint32_t dst = smb + (arr ? SM_RB_LO : SM_RB_HI)
                     + chunk * 4096 + row * 128 + ((seg ^ (row & 7)) << 4);
        CP_ASYNC16(dst, src);
    }
    CP_COMMIT();
    CP_WAIT0();
    __syncthreads();

    for (int t = 0; t < T; t++) {
        // neighbor sync: wait for mg-1, mg, mg+1 to finish step t-1
        if (t > 0) {
            if (tid < 3) {
                int mgn = mg + tid - 1;
                if (mgn < 0) mgn = 0;
                if (mgn > 7) mgn = 7;
                const unsigned tgt = 15u * (unsigned)t;
                while (g_sync[mgn] < tgt) { }
            }
            __syncthreads();
        }

        // ---- stage compact halo from xtp[t-1] (group 0, gated before MMA) ----
        if (t > 0) {
            const __nv_bfloat16* baseHi = g_xtp_hi + ((size_t)(t - 1) * RPAD + l0) * CPAD;
            const __nv_bfloat16* baseLo = g_xtp_lo + ((size_t)(t - 1) * RPAD + l0) * CPAD;
            for (int u = tid; u < 2584; u += RTHR) {
                int arr = u >= 1292;
                int v = arr ? u - 1292 : u;
                const __nv_bfloat16* src = (arr ? baseLo : baseHi) + v * 8;
                uint32_t dst = smb + SM_RA + arr * HALO_B + v * 16;
                CP_ASYNC16(dst, src);
            }
            CP_COMMIT();
        }
        // ---- prefetch xi gate slice (group 1, only needed at epilogue) ----
        {
            const float* xibase = xi + ((size_t)t * L + l0) * J3P + c0;
            for (int u = tid; u < 960; u += RTHR) {
                int lr = u / 15, rem = u - lr * 15;
                int gate = rem / 5, seg = rem - gate * 5;
                const float* src = xibase + (size_t)lr * J3P + gate * HID + seg * 2;
                uint32_t dst = smb + SM_XI + lr * 128 + gate * 40 + seg * 8;
                CP_ASYNC8(dst, src);
            }
            CP_COMMIT();
        }
        if (t > 0) CP_WAIT1();   // halo complete; xi may still be in flight
        __syncthreads();

        float acc[2][4][4];   // 2 m16-tiles x 4 n8-tiles x 4 regs
        #pragma unroll
        for (int mt = 0; mt < 2; mt++)
            #pragma unroll
            for (int nt = 0; nt < 4; nt++)
                #pragma unroll
                for (int k = 0; k < 4; k++) acc[mt][nt][k] = 0.f;

        const uint32_t aHi0 = smb + SM_RA + aLane0;
        const uint32_t aHi1 = smb + SM_RA + aLane1;
        const int kcBeg = kw * 2;

        #pragma unroll
        for (int kc2 = 0; kc2 < 2; kc2++) {
            const int kc = kcBeg + kc2;
            const uint32_t bBh = smb + SM_RB_HI + kc * 4096;
            const uint32_t bBl = smb + SM_RB_LO + kc * 4096;
            #pragma unroll
            for (int ks = 0; ks < 4; ks++) {
                uint32_t aoff = kc * 128 + ks * 32;
                uint32_t ah[2][4], al[2][4];
                LDSM_X4(ah[0][0], ah[0][1], ah[0][2], ah[0][3], aHi0 + aoff);
                LDSM_X4(ah[1][0], ah[1][1], ah[1][2], ah[1][3], aHi1 + aoff);
                LDSM_X4(al[0][0], al[0][1], al[0][2], al[0][3], aHi0 + HALO_B + aoff);
                LDSM_X4(al[1][0], al[1][1], al[1][2], al[1][3], aHi1 + HALO_B + aoff);
                uint32_t bko = (((2 * ks + jB) ^ bXor) << 4);
                uint32_t bh[8], bl[8];
                LDSM_X4(bh[0], bh[1], bh[2], bh[3], bBh + bRowOff0 + bko);
                LDSM_X4(bh[4], bh[5], bh[6], bh[7], bBh + bRowOff1 + bko);
                LDSM_X4(bl[0], bl[1], bl[2], bl[3], bBl + bRowOff0 + bko);
                LDSM_X4(bl[4], bl[5], bl[6], bl[7], bBl + bRowOff1 + bko);
                #pragma unroll
                for (int mt = 0; mt < 2; mt++) {
                    #pragma unroll
                    for (int j = 0; j < 4; j++) {
                        float* d = acc[mt][j];
                        MMA16816(d, ah[mt][0], ah[mt][1], ah[mt][2], ah[mt][3], bh[2 * j], bh[2 * j + 1]);
                        MMA16816(d, al[mt][0], al[mt][1], al[mt][2], al[mt][3], bh[2 * j], bh[2 * j + 1]);
                        MMA16816(d, ah[mt][0], ah[mt][1], ah[mt][2], ah[mt][3], bl[2 * j], bl[2 * j + 1]);
                    }
                }
            }
        }

        // ---- stage hh partials into this K-group's smem buffer ----
        {
            const int g = lane >> 2, tq = lane & 3;
            #pragma unroll
            for (int mt = 0; mt < 2; mt++) {
                int r0 = m0w + mt * 16 + g;
                int r1 = r0 + 8;
                #pragma unroll
                for (int j = 0; j < 4; j++) {
                    int col = j * 8 + tq * 2;
                    sh_hh_my[r0 * 32 + col]     = acc[mt][j][0];
                    sh_hh_my[r0 * 32 + col + 1] = acc[mt][j][1];
                    sh_hh_my[r1 * 32 + col]     = acc[mt][j][2];
                    sh_hh_my[r1 * 32 + col + 1] = acc[mt][j][3];
                }
            }
        }
        CP_WAIT0();       // xi slice now resident
        __syncthreads();

        // ---- gate epilogue: 64 rows x 10 channels, all smem-sourced ----
        {
            const float* hh = reinterpret_cast<float*>(sm + SM_RHH);
            for (int e = tid; e < 640; e += RTHR) {
                int lr = e / 10, ch = e - lr * 10;
                int l = l0 + lr, c = c0 + ch;
                int b = lr * 32;
                float hr = 0.f, hz = 0.f, hn = 0.f;
                #pragma unroll
                for (int p = 0; p < 6; p++) {
                    const float* hp = hh + p * 2048;
                    hr += hp[b + ch];
                    hz += hp[b + 10 + ch];
                    hn += hp[b + 20 + ch];
                }
                const float* qx = sh_xi + lr * 32;
                float xr = qx[ch], xz = qx[10 + ch], xn = qx[20 + ch];
                // h_prev reconstructed from the staged halo (hi+lo)
                uint32_t hoff = (uint32_t)(lr + 2) * 304 + 2u * (uint32_t)c;
                float hpv =
                    __bfloat162float(*reinterpret_cast<__nv_bfloat16*>(sm + SM_RA + hoff)) +
                    __bfloat162float(*reinterpret_cast<__nv_bfloat16*>(sm + SM_RA + HALO_B + hoff));
                float r = sigf(xr + hr);
                float z = sigf(xz + hz);
                float n = tanhfast(xn + r * hn);
                float hnew = n + z * (hpv - n);

                __nv_bfloat16 hi = __float2bfloat16(hnew);
                __nv_bfloat16 lo = __float2bfloat16(hnew - __bfloat162float(hi));
                size_t xidx = ((size_t)t * RPAD + (l + 2)) * CPAD + c;
                g_xtp_hi[xidx] = hi;
                g_xtp_lo[xidx] = lo;
                if (layer == 1)
                    outp[((size_t)l * T + t) * HID + c] = hnew;
            }
        }

        // signal completion of step t (proven R12 scheme)
        __threadfence();
        __syncthreads();
        if (tid == 0) atomicAdd((unsigned*)&g_sync[mg], 1u);
    }
}

// =====================================================================
extern "C" void kernel_launch(void* const* d_in, const int* in_sizes, int n_in,
                              void* d_out, int out_size)
{
    (void)in_sizes; (void)n_in; (void)out_size;
    const float* xs  = (const float*)d_in[0];
    const float* Wi0 = (const float*)d_in[1];
    const float* bi0 = (const float*)d_in[2];
    const float* Wh0 = (const float*)d_in[3];
    const float* Wi1 = (const float*)d_in[4];
    const float* bi1 = (const float*)d_in[5];
    const float* Wh1 = (const float*)d_in[6];
    float* out = (float*)d_out;

    float* xi;
    cudaGetSymbolAddress((void**)&xi, g_xi);

    const size_t smem_mma = 2 * BUFSZ;
    static int attr_done = 0;
    if (!attr_done) {
        cudaFuncSetAttribute(xi_mma_kernel, cudaFuncAttributeMaxDynamicSharedMemorySize, (int)smem_mma);
        cudaFuncSetAttribute(rec_mma_kernel, cudaFuncAttributeMaxDynamicSharedMemorySize, SM_REC_TOTAL);
        attr_done = 1;
    }

    const size_t n_prep_x = (size_t)T * RPAD * CPAD;
    const int    gx = (int)((n_prep_x + 255) / 256);
    const size_t n_prep_wb = (size_t)(NB + 480) * KPAD;
    const int    gwb = (int)((n_prep_wb + 255) / 256);
    const dim3 grid_mma(T, 4, 4);
    const dim3 grid_rec(15, 8);

    for (int layer = 0; layer < 2; layer++) {
        const float* Wi = layer ? Wi1 : Wi0;
        const float* bi = layer ? bi1 : bi0;
        const float* Wh = layer ? Wh1 : Wh0;

        if (layer == 0) prep_x_kernel<<<gx, 256>>>(xs);
        prep_wb_kernel<<<gwb, 256>>>(Wi, Wh);
        xi_mma_kernel<<<grid_mma, 512, smem_mma>>>(bi, xi);
        rec_mma_kernel<<<grid_rec, RTHR, SM_REC_TOTAL>>>(xi, out, layer);
    }
}

// round 15
// speedup vs baseline: 1.2077x; 1.0328x over previous
#include <cuda_runtime.h>
#include <cuda_bf16.h>
#include <math.h>
#include <stdint.h>

#define L    512
#define T    96
#define CIN  150
#define HID  150
#define J3   450
#define J3P  480
#define KW   5

// padded GEMM geometry (flat sliding-window im2col)
#define CPAD   152            // padded channel stride (150 + 2)
#define KPAD   768            // 5*152 = 760 -> pad to 768 = 12 chunks of 64
#define KC     64
#define NKC    12
#define RPAD   520
#define NB     512            // xi B padded N

// ---------------- scratch ----------------
__device__ float g_xi [(size_t)T * L * J3P];
__device__ volatile unsigned g_sync[8];
// xtp doubles as the h-history for the recurrent pass: slice t holds
// h_t (layer's hidden state after step t) in padded bf16 hi/lo form.
__device__ __align__(256) __nv_bfloat16 g_xtp_hi[(size_t)T * RPAD * CPAD];
__device__ __align__(256) __nv_bfloat16 g_xtp_lo[(size_t)T * RPAD * CPAD];
__device__ __align__(256) __nv_bfloat16 g_B_hi[(size_t)NB * KPAD];
__device__ __align__(256) __nv_bfloat16 g_B_lo[(size_t)NB * KPAD];
__device__ __align__(256) __nv_bfloat16 g_Br_hi[480 * KPAD];
__device__ __align__(256) __nv_bfloat16 g_Br_lo[480 * KPAD];

extern __shared__ float smem[];

// ---------------- PTX helpers (baseline ISA only) ----------------
__device__ __forceinline__ uint32_t smem_u32(const void* p) {
    uint32_t a;
    asm("{ .reg .u64 t; cvta.to.shared.u64 t, %1; cvt.u32.u64 %0, t; }" : "=r"(a) : "l"(p));
    return a;
}
#define CP_ASYNC16(dst, src) \
    asm volatile("cp.async.cg.shared.global [%0], [%1], 16;" :: "r"(dst), "l"(src))
#define CP_ASYNC8(dst, src) \
    asm volatile("cp.async.ca.shared.global [%0], [%1], 8;" :: "r"(dst), "l"(src))
#define CP_COMMIT() asm volatile("cp.async.commit_group;")
#define CP_WAIT1()  asm volatile("cp.async.wait_group 1;")
#define CP_WAIT0()  asm volatile("cp.async.wait_group 0;")
#define LDSM_X4(r0,r1,r2,r3,a) \
    asm volatile("ldmatrix.sync.aligned.m8n8.x4.shared.b16 {%0,%1,%2,%3}, [%4];" \
        : "=r"(r0),"=r"(r1),"=r"(r2),"=r"(r3) : "r"(a))
#define MMA16816(d,a0,a1,a2,a3,b0,b1) \
    asm volatile("mma.sync.aligned.m16n8k16.row.col.f32.bf16.bf16.f32 " \
        "{%0,%1,%2,%3},{%4,%5,%6,%7},{%8,%9},{%0,%1,%2,%3};" \
        : "+f"((d)[0]),"+f"((d)[1]),"+f"((d)[2]),"+f"((d)[3]) \
        : "r"(a0),"r"(a1),"r"(a2),"r"(a3),"r"(b0),"r"(b1))

__device__ __forceinline__ void signal_release(unsigned* addr) {
    asm volatile("red.release.gpu.global.add.u32 [%0], %1;"
                 :: "l"(addr), "r"(1u) : "memory");
}
__device__ __forceinline__ unsigned ld_acquire(const unsigned* addr) {
    unsigned v;
    asm volatile("ld.acquire.gpu.global.u32 %0, [%1];"
                 : "=r"(v) : "l"(addr) : "memory");
    return v;
}

__device__ __forceinline__ float sigf(float x) {
    float e = __expf(-x);
    return __fdividef(1.f, 1.f + e);
}
__device__ __forceinline__ float tanhfast(float x) {
    return 2.f * sigf(2.f * x) - 1.f;
}

// =====================================================================
// prep kernels (R12)
// =====================================================================
__global__ void prep_x_kernel(const float* __restrict__ x) {
    size_t i = (size_t)blockIdx.x * blockDim.x + threadIdx.x;
    const size_t Ntot = (size_t)T * RPAD * CPAD;
    if (i >= Ntot) return;
    int c = i % CPAD;
    int r = (i / CPAD) % RPAD;
    int t = i / ((size_t)CPAD * RPAD);
    float v = 0.f;
    if (r >= 2 && r < 2 + L && c < CIN)
        v = x[(((size_t)(r - 2)) * T + t) * CIN + c];
    __nv_bfloat16 hi = __float2bfloat16(v);
    __nv_bfloat16 lo = __float2bfloat16(v - __bfloat162float(hi));
    g_xtp_hi[i] = hi;
    g_xtp_lo[i] = lo;
}

__global__ void prep_wb_kernel(const float* __restrict__ Wi,
                               const float* __restrict__ Wh) {
    if (blockIdx.x == 0 && threadIdx.x < 8) g_sync[threadIdx.x] = 0u;
    size_t i = (size_t)blockIdx.x * blockDim.x + threadIdx.x;
    const size_t Ntot = (size_t)(NB + 480) * KPAD;
    if (i >= Ntot) return;
    int k = i % KPAD;
    int n = i / KPAD;
    int tap = k / CPAD, c = k % CPAD;
    float v = 0.f;
    if (n < NB) {
        if (n < J3 && tap < KW && c < CIN)
            v = Wi[((size_t)tap * CIN + c) * J3 + n];
        __nv_bfloat16 hi = __float2bfloat16(v);
        __nv_bfloat16 lo = __float2bfloat16(v - __bfloat162float(hi));
        g_B_hi[(size_t)n * KPAD + k] = hi;
        g_B_lo[(size_t)n * KPAD + k] = lo;
    } else {
        int n2 = n - NB;
        int cg = n2 >> 5, j = n2 & 31;
        if (j < 30 && tap < KW && c < CIN) {
            int gate = j / 10, ch = j - gate * 10;
            v = Wh[((size_t)tap * CIN + c) * J3 + gate * HID + cg * 10 + ch];
        }
        __nv_bfloat16 hi = __float2bfloat16(v);
        __nv_bfloat16 lo = __float2bfloat16(v - __bfloat162float(hi));
        g_Br_hi[(size_t)n2 * KPAD + k] = hi;
        g_Br_lo[(size_t)n2 * KPAD + k] = lo;
    }
}

// =====================================================================
// xi via mma.sync bf16 split (R12-proven): grid (96,4,4), 512 thr,
// 2-buffer cp.async double-buffering, warp tile 32x32 (4mw x 4nw).
// =====================================================================
#define BUFSZ 65536

__global__ __launch_bounds__(512, 1) void xi_mma_kernel(
    const float* __restrict__ bi, float* __restrict__ xi)
{
    char* sm = reinterpret_cast<char*>(smem);
    const uint32_t smb = smem_u32(sm);
    const int tid = threadIdx.x;
    const int lane = tid & 31, wid = tid >> 5;
    const int t = blockIdx.x, mblk = blockIdx.y, nblk = blockIdx.z;

    const int mw = wid & 3, nw = wid >> 2;   // 4 x 4 warps
    const int m0 = mw * 32, n0 = nw * 32;

    int aRow[2], aXor[2];
    const int jA = (lane >> 4) & 1;
    #pragma unroll
    for (int mt = 0; mt < 2; mt++) {
        aRow[mt] = (m0 + mt * 16 + (lane & 15)) * 128;
        aXor[mt] = ((m0 + mt * 16 + (lane & 15)) & 7);
    }
    int bRow[2], bXor[2];
    const int jB = (lane >> 3) & 1;
    #pragma unroll
    for (int np = 0; np < 2; np++) {
        int r = n0 + np * 16 + (lane & 7) + ((lane >> 4) & 1) * 8;
        bRow[np] = r * 128;
        bXor[np] = r & 7;
    }

    const __nv_bfloat16* srcA_hi = g_xtp_hi + ((size_t)t * RPAD + (size_t)mblk * 128) * CPAD;
    const __nv_bfloat16* srcA_lo = g_xtp_lo + ((size_t)t * RPAD + (size_t)mblk * 128) * CPAD;
    const __nv_bfloat16* srcB_hi = g_B_hi + (size_t)nblk * 128 * KPAD;
    const __nv_bfloat16* srcB_lo = g_B_lo + (size_t)nblk * 128 * KPAD;

    float acc[2][4][4];
    #pragma unroll
    for (int mt = 0; mt < 2; mt++)
        #pragma unroll
        for (int nt = 0; nt < 4; nt++)
            #pragma unroll
            for (int k = 0; k < 4; k++) acc[mt][nt][k] = 0.f;

    auto stage = [&](int kc, int buf) {
        const uint32_t base = smb + buf * BUFSZ;
        #pragma unroll
        for (int it = 0; it < 8; it++) {
            int u = it * 512 + tid;
            int arr = u >> 10;
            int v = u & 1023;
            int row = v >> 3, seg = v & 7;
            const __nv_bfloat16* src;
            if (arr == 0)      src = srcA_hi + (size_t)row * CPAD + kc * KC + seg * 8;
            else if (arr == 1) src = srcA_lo + (size_t)row * CPAD + kc * KC + seg * 8;
            else if (arr == 2) src = srcB_hi + (size_t)row * KPAD + kc * KC + seg * 8;
            else               src = srcB_lo + (size_t)row * KPAD + kc * KC + seg * 8;
            uint32_t dst = base + arr * 16384 + row * 128 + ((seg ^ (row & 7)) << 4);
            CP_ASYNC16(dst, src);
        }
    };

    stage(0, 0);
    CP_COMMIT();

    for (int kc = 0; kc < NKC; kc++) {
        const int buf = kc & 1;
        if (kc + 1 < NKC) {
            stage(kc + 1, buf ^ 1);
            CP_COMMIT();
            CP_WAIT1();
        } else {
            CP_WAIT0();
        }
        __syncthreads();

        const uint32_t bA_hi = smb + buf * BUFSZ;
        const uint32_t bA_lo = bA_hi + 16384;
        const uint32_t bB_hi = bA_hi + 32768;
        const uint32_t bB_lo = bA_hi + 49152;

        #pragma unroll
        for (int ks = 0; ks < 4; ks++) {
            uint32_t ah[2][4], al[2][4];
            #pragma unroll
            for (int mt = 0; mt < 2; mt++) {
                uint32_t off = aRow[mt] + (((2 * ks + jA) ^ aXor[mt]) << 4);
                LDSM_X4(ah[mt][0], ah[mt][1], ah[mt][2], ah[mt][3], bA_hi + off);
                LDSM_X4(al[mt][0], al[mt][1], al[mt][2], al[mt][3], bA_lo + off);
            }
            #pragma unroll
            for (int np = 0; np < 2; np++) {
                if (nblk * 128 + n0 + np * 16 >= J3) continue;
                uint32_t off = bRow[np] + (((2 * ks + jB) ^ bXor[np]) << 4);
                uint32_t bh[4], bl[4];
                LDSM_X4(bh[0], bh[1], bh[2], bh[3], bB_hi + off);
                LDSM_X4(bl[0], bl[1], bl[2], bl[3], bB_lo + off);
                #pragma unroll
                for (int mt = 0; mt < 2; mt++) {
                    float* d0 = acc[mt][np * 2];
                    float* d1 = acc[mt][np * 2 + 1];
                    MMA16816(d0, ah[mt][0], ah[mt][1], ah[mt][2], ah[mt][3], bh[0], bh[1]);
                    MMA16816(d0, al[mt][0], al[mt][1], al[mt][2], al[mt][3], bh[0], bh[1]);
                    MMA16816(d0, ah[mt][0], ah[mt][1], ah[mt][2], ah[mt][3], bl[0], bl[1]);
                    MMA16816(d1, ah[mt][0], ah[mt][1], ah[mt][2], ah[mt][3], bh[2], bh[3]);
                    MMA16816(d1, al[mt][0], al[mt][1], al[mt][2], al[mt][3], bh[2], bh[3]);
                    MMA16816(d1, ah[mt][0], ah[mt][1], ah[mt][2], ah[mt][3], bl[2], bl[3]);
                }
            }
        }
        __syncthreads();
    }

    const int g  = lane >> 2;
    const int tq = lane & 3;
    #pragma unroll
    for (int mt = 0; mt < 2; mt++) {
        int r0 = mblk * 128 + m0 + mt * 16 + g;
        int r1 = r0 + 8;
        float* row0 = xi + ((size_t)t * L + r0) * J3P;
        float* row1 = xi + ((size_t)t * L + r1) * J3P;
        #pragma unroll
        for (int nt = 0; nt < 4; nt++) {
            int j0 = nblk * 128 + n0 + nt * 8 + tq * 2;
            if (j0 < J3) {
                float b0 = bi[j0], b1 = bi[j0 + 1];
                float2 v0 = make_float2(acc[mt][nt][0] + b0, acc[mt][nt][1] + b1);
                float2 v1 = make_float2(acc[mt][nt][2] + b0, acc[mt][nt][3] + b1);
                *reinterpret_cast<float2*>(row0 + j0) = v0;
                *reinterpret_cast<float2*>(row1 + j0) = v1;
            }
        }
    }
}

// =====================================================================
// Persistent recurrent MMA kernel, v9 = R12 structure (best measured)
// with lighter sync:
//  - release: __syncthreads() then tid0 red.release.gpu (no MEMBAR.ALL)
//  - poll: tid<3 ld.acquire.gpu (3 loads/block/step; sound with release)
// grid (15 cg, 8 mg) = 120 blocks, 512 thr = 16 warps as 4mw x 4kw.
// =====================================================================
#define SM_RB_HI 0
#define SM_RB_LO 49152
#define SM_RA    98304
#define HALO_B   20736          // 68*304 = 20672, rounded up to 128
#define SM_RHH   (SM_RA + 2 * HALO_B)          // 139776 (4 x 8192)
#define SM_XI    (SM_RHH + 32768)              // 172544
#define SM_REC_TOTAL (SM_XI + 8192)            // 180736

__global__ __launch_bounds__(512, 1) void rec_mma_kernel(
    const float* __restrict__ xi, float* __restrict__ outp, int layer)
{
    char* sm = reinterpret_cast<char*>(smem);
    const uint32_t smb = smem_u32(sm);
    float* sh_hh0 = reinterpret_cast<float*>(sm + SM_RHH);
    float* sh_hh1 = reinterpret_cast<float*>(sm + SM_RHH + 8192);
    float* sh_hh2 = reinterpret_cast<float*>(sm + SM_RHH + 16384);
    float* sh_hh3 = reinterpret_cast<float*>(sm + SM_RHH + 24576);
    float* sh_xi  = reinterpret_cast<float*>(sm + SM_XI);
    const int tid = threadIdx.x;
    const int lane = tid & 31, wid = tid >> 5;
    const int cg = blockIdx.x, mg = blockIdx.y;
    const int c0 = cg * 10;
    const int l0 = mg * 64;

    const int mw = wid & 3;             // 4 m-warps (16 rows each)
    const int kw = wid >> 2;            // 4 K-split groups (3 kc each)
    const int m0w = mw * 16;
    float* sh_hh_my = (kw == 0) ? sh_hh0 : (kw == 1) ? sh_hh1
                     : (kw == 2) ? sh_hh2 : sh_hh3;

    // A lane offset into compact halo (row stride 304B, k-half select jA)
    const int jA = (lane >> 4) & 1;
    const uint32_t aLane = (uint32_t)(m0w + (lane & 15)) * 304 + jA * 16;
    // B lane addressing (swizzled resident buffer), two n16 groups
    const int bR = (lane & 7) + ((lane >> 4) & 1) * 8;   // rows 0..15
    const int bRowOff0 = bR * 128;
    const int bRowOff1 = (bR + 16) * 128;                // (bR+16)&7 == bR&7
    const int bXor = bR & 7;
    const int jB = (lane >> 3) & 1;

    // ---- zero-init the entire halo region ONCE (t=0 state + K-pad tail) ----
    {
        uint4 z = make_uint4(0, 0, 0, 0);
        for (int u = tid; u < (2 * HALO_B) / 16; u += 512)
            *reinterpret_cast<uint4*>(sm + SM_RA + u * 16) = z;
    }

    // ---- load resident B (weights) once: 2 arr x 12 chunks x 32 rows x 8 segs ----
    for (int u = tid; u < 6144; u += 512) {
        int arr = u / 3072;
        int v = u - arr * 3072;
        int chunk = v >> 8;
        int w = v & 255;
        int row = w >> 3, seg = w & 7;
        const __nv_bfloat16* src =
            (arr ? g_Br_lo : g_Br_hi) + ((size_t)(cg * 32 + row)) * KPAD + chunk * KC + seg * 8;
        uint32_t dst = smb + (arr ? SM_RB_LO : SM_RB_HI)
                     + chunk * 4096 + row * 128 + ((seg ^ (row & 7)) << 4);
        CP_ASYNC16(dst, src);
    }
    CP_COMMIT();
    CP_WAIT0();
    __syncthreads();

    for (int t = 0; t < T; t++) {
        // neighbor sync: tid<3 poll mg-1, mg, mg+1 with acquire loads,
        // then block barrier (contention-free: 3 loads per block).
        if (t > 0) {
            if (tid < 3) {
                int mgn = mg + tid - 1;
                if (mgn < 0) mgn = 0;
                if (mgn > 7) mgn = 7;
                const unsigned tgt = 15u * (unsigned)t;
                while (ld_acquire((const unsigned*)&g_sync[mgn]) < tgt) { }
            }
            __syncthreads();
        }

        // ---- stage compact halo from xtp[t-1] (group 0, gated before MMA) ----
        if (t > 0) {
            const __nv_bfloat16* baseHi = g_xtp_hi + ((size_t)(t - 1) * RPAD + l0) * CPAD;
            const __nv_bfloat16* baseLo = g_xtp_lo + ((size_t)(t - 1) * RPAD + l0) * CPAD;
            for (int u = tid; u < 2584; u += 512) {
                int arr = u >= 1292;
                int v = arr ? u - 1292 : u;
                const __nv_bfloat16* src = (arr ? baseLo : baseHi) + v * 8;
                uint32_t dst = smb + SM_RA + arr * HALO_B + v * 16;
                CP_ASYNC16(dst, src);
            }
            CP_COMMIT();
        }
        // ---- prefetch xi gate slice (group 1, only needed at epilogue) ----
        {
            const float* xibase = xi + ((size_t)t * L + l0) * J3P + c0;
            for (int u = tid; u < 960; u += 512) {
                int lr = u / 15, rem = u - lr * 15;
                int gate = rem / 5, seg = rem - gate * 5;
                const float* src = xibase + (size_t)lr * J3P + gate * HID + seg * 2;
                uint32_t dst = smb + SM_XI + lr * 128 + gate * 40 + seg * 8;
                CP_ASYNC8(dst, src);
            }
            CP_COMMIT();
        }
        if (t > 0) CP_WAIT1();   // halo complete; xi may still be in flight
        __syncthreads();

        float a0[4][4];   // 4 n8-tiles x 4 regs
        #pragma unroll
        for (int nt = 0; nt < 4; nt++)
            #pragma unroll
            for (int k = 0; k < 4; k++) a0[nt][k] = 0.f;

        const uint32_t aHi = smb + SM_RA + aLane;
        const uint32_t aLo = aHi + HALO_B;
        const int kcBeg = kw * 3;

        #pragma unroll
        for (int kc2 = 0; kc2 < 3; kc2++) {
            const int kc = kcBeg + kc2;
            const uint32_t bBh = smb + SM_RB_HI + kc * 4096;
            const uint32_t bBl = smb + SM_RB_LO + kc * 4096;
            #pragma unroll
            for (int ks = 0; ks < 4; ks++) {
                uint32_t aoff = kc * 128 + ks * 32;
                uint32_t ah[4], al[4];
                LDSM_X4(ah[0], ah[1], ah[2], ah[3], aHi + aoff);
                LDSM_X4(al[0], al[1], al[2], al[3], aLo + aoff);
                uint32_t bko = (((2 * ks + jB) ^ bXor) << 4);
                uint32_t bh[8], bl[8];
                LDSM_X4(bh[0], bh[1], bh[2], bh[3], bBh + bRowOff0 + bko);
                LDSM_X4(bh[4], bh[5], bh[6], bh[7], bBh + bRowOff1 + bko);
                LDSM_X4(bl[0], bl[1], bl[2], bl[3], bBl + bRowOff0 + bko);
                LDSM_X4(bl[4], bl[5], bl[6], bl[7], bBl + bRowOff1 + bko);
                #pragma unroll
                for (int j = 0; j < 4; j++) {
                    float* d = a0[j];
                    MMA16816(d, ah[0], ah[1], ah[2], ah[3], bh[2 * j], bh[2 * j + 1]);
                    MMA16816(d, al[0], al[1], al[2], al[3], bh[2 * j], bh[2 * j + 1]);
                    MMA16816(d, ah[0], ah[1], ah[2], ah[3], bl[2 * j], bl[2 * j + 1]);
                }
            }
        }

        // ---- stage hh partials into this K-group's smem buffer ----
        {
            const int g = lane >> 2, tq = lane & 3;
            int r0 = m0w + g;
            int r1 = r0 + 8;
            #pragma unroll
            for (int j = 0; j < 4; j++) {
                int col = j * 8 + tq * 2;
                sh_hh_my[r0 * 32 + col]     = a0[j][0];
                sh_hh_my[r0 * 32 + col + 1] = a0[j][1];
                sh_hh_my[r1 * 32 + col]     = a0[j][2];
                sh_hh_my[r1 * 32 + col + 1] = a0[j][3];
            }
        }
        CP_WAIT0();       // xi slice now resident
        __syncthreads();

        // ---- gate epilogue: 64 rows x 10 channels, all smem-sourced ----
        {
            for (int e = tid; e < 640; e += 512) {
                int lr = e / 10, ch = e - lr * 10;
                int l = l0 + lr, c = c0 + ch;
                int b = lr * 32;
                float hr = sh_hh0[b + ch]      + sh_hh1[b + ch]
                         + sh_hh2[b + ch]      + sh_hh3[b + ch];
                float hz = sh_hh0[b + 10 + ch] + sh_hh1[b + 10 + ch]
                         + sh_hh2[b + 10 + ch] + sh_hh3[b + 10 + ch];
                float hn = sh_hh0[b + 20 + ch] + sh_hh1[b + 20 + ch]
                         + sh_hh2[b + 20 + ch] + sh_hh3[b + 20 + ch];
                const float* qx = sh_xi + lr * 32;
                float xr = qx[ch], xz = qx[10 + ch], xn = qx[20 + ch];
                // h_prev reconstructed from the staged halo (hi+lo)
                uint32_t hoff = (uint32_t)(lr + 2) * 304 + 2u * (uint32_t)c;
                float hpv =
                    __bfloat162float(*reinterpret_cast<__nv_bfloat16*>(sm + SM_RA + hoff)) +
                    __bfloat162float(*reinterpret_cast<__nv_bfloat16*>(sm + SM_RA + HALO_B + hoff));
                float r = sigf(xr + hr);
                float z = sigf(xz + hz);
                float n = tanhfast(xn + r * hn);
                float hnew = n + z * (hpv - n);

                __nv_bfloat16 hi = __float2bfloat16(hnew);
                __nv_bfloat16 lo = __float2bfloat16(hnew - __bfloat162float(hi));
                size_t xidx = ((size_t)t * RPAD + (l + 2)) * CPAD + c;
                g_xtp_hi[xidx] = hi;
                g_xtp_lo[xidx] = lo;
                if (layer == 1)
                    outp[((size_t)l * T + t) * HID + c] = hnew;
            }
        }

        // signal completion of step t: block barrier orders all threads'
        // stores before tid0's release-reduction (no MEMBAR.ALL needed).
        __syncthreads();
        if (tid == 0) signal_release((unsigned*)&g_sync[mg]);
    }
}

// =====================================================================
extern "C" void kernel_launch(void* const* d_in, const int* in_sizes, int n_in,
                              void* d_out, int out_size)
{
    (void)in_sizes; (void)n_in; (void)out_size;
    const float* xs  = (const float*)d_in[0];
    const float* Wi0 = (const float*)d_in[1];
    const float* bi0 = (const float*)d_in[2];
    const float* Wh0 = (const float*)d_in[3];
    const float* Wi1 = (const float*)d_in[4];
    const float* bi1 = (const float*)d_in[5];
    const float* Wh1 = (const float*)d_in[6];
    float* out = (float*)d_out;

    float* xi;
    cudaGetSymbolAddress((void**)&xi, g_xi);

    const size_t smem_mma = 2 * BUFSZ;
    static int attr_done = 0;
    if (!attr_done) {
        cudaFuncSetAttribute(xi_mma_kernel, cudaFuncAttributeMaxDynamicSharedMemorySize, (int)smem_mma);
        cudaFuncSetAttribute(rec_mma_kernel, cudaFuncAttributeMaxDynamicSharedMemorySize, SM_REC_TOTAL);
        attr_done = 1;
    }

    const size_t n_prep_x = (size_t)T * RPAD * CPAD;
    const int    gx = (int)((n_prep_x + 255) / 256);
    const size_t n_prep_wb = (size_t)(NB + 480) * KPAD;
    const int    gwb = (int)((n_prep_wb + 255) / 256);
    const dim3 grid_mma(T, 4, 4);
    const dim3 grid_rec(15, 8);

    for (int layer = 0; layer < 2; layer++) {
        const float* Wi = layer ? Wi1 : Wi0;
        const float* bi = layer ? bi1 : bi0;
        const float* Wh = layer ? Wh1 : Wh0;

        if (layer == 0) prep_x_kernel<<<gx, 256>>>(xs);
        prep_wb_kernel<<<gwb, 256>>>(Wi, Wh);
        xi_mma_kernel<<<grid_mma, 512, smem_mma>>>(bi, xi);
        rec_mma_kernel<<<grid_rec, 512, SM_REC_TOTAL>>>(xi, out, layer);
    }
}

// round 17
// speedup vs baseline: 1.2421x; 1.0285x over previous
#include <cuda_runtime.h>
#include <cuda_bf16.h>
#include <math.h>
#include <stdint.h>

#define L    512
#define T    96
#define CIN  150
#define HID  150
#define J3   450
#define J3P  480
#define KW   5

// padded GEMM geometry (flat sliding-window im2col)
#define CPAD   152            // padded channel stride (150 + 2)
#define KPAD   768            // 5*152 = 760 -> pad to 768 = 12 chunks of 64
#define KC     64
#define NKC    12
#define RPAD   520
#define NB     512            // xi B padded N

// ---------------- scratch ----------------
__device__ float g_xi [(size_t)T * L * J3P];
__device__ volatile unsigned g_sync[8];
// xtp doubles as the h-history for the recurrent pass: slice t holds
// h_t (layer's hidden state after step t) in padded bf16 hi/lo form.
__device__ __align__(256) __nv_bfloat16 g_xtp_hi[(size_t)T * RPAD * CPAD];
__device__ __align__(256) __nv_bfloat16 g_xtp_lo[(size_t)T * RPAD * CPAD];
__device__ __align__(256) __nv_bfloat16 g_B_hi[(size_t)NB * KPAD];
__device__ __align__(256) __nv_bfloat16 g_B_lo[(size_t)NB * KPAD];
__device__ __align__(256) __nv_bfloat16 g_Br_hi[480 * KPAD];
__device__ __align__(256) __nv_bfloat16 g_Br_lo[480 * KPAD];

extern __shared__ float smem[];

// ---------------- PTX helpers (baseline ISA only) ----------------
__device__ __forceinline__ uint32_t smem_u32(const void* p) {
    uint32_t a;
    asm("{ .reg .u64 t; cvta.to.shared.u64 t, %1; cvt.u32.u64 %0, t; }" : "=r"(a) : "l"(p));
    return a;
}
#define CP_ASYNC16(dst, src) \
    asm volatile("cp.async.cg.shared.global [%0], [%1], 16;" :: "r"(dst), "l"(src))
#define CP_ASYNC8(dst, src) \
    asm volatile("cp.async.ca.shared.global [%0], [%1], 8;" :: "r"(dst), "l"(src))
#define CP_COMMIT() asm volatile("cp.async.commit_group;")
#define CP_WAIT1()  asm volatile("cp.async.wait_group 1;")
#define CP_WAIT0()  asm volatile("cp.async.wait_group 0;")
#define LDSM_X4(r0,r1,r2,r3,a) \
    asm volatile("ldmatrix.sync.aligned.m8n8.x4.shared.b16 {%0,%1,%2,%3}, [%4];" \
        : "=r"(r0),"=r"(r1),"=r"(r2),"=r"(r3) : "r"(a))
#define MMA16816(d,a0,a1,a2,a3,b0,b1) \
    asm volatile("mma.sync.aligned.m16n8k16.row.col.f32.bf16.bf16.f32 " \
        "{%0,%1,%2,%3},{%4,%5,%6,%7},{%8,%9},{%0,%1,%2,%3};" \
        : "+f"((d)[0]),"+f"((d)[1]),"+f"((d)[2]),"+f"((d)[3]) \
        : "r"(a0),"r"(a1),"r"(a2),"r"(a3),"r"(b0),"r"(b1))

__device__ __forceinline__ void signal_release(unsigned* addr) {
    asm volatile("red.release.gpu.global.add.u32 [%0], %1;"
                 :: "l"(addr), "r"(1u) : "memory");
}
__device__ __forceinline__ unsigned ld_acquire(const unsigned* addr) {
    unsigned v;
    asm volatile("ld.acquire.gpu.global.u32 %0, [%1];"
                 : "=r"(v) : "l"(addr) : "memory");
    return v;
}

__device__ __forceinline__ float sigf(float x) {
    float e = __expf(-x);
    return __fdividef(1.f, 1.f + e);
}
__device__ __forceinline__ float tanhfast(float x) {
    return 2.f * sigf(2.f * x) - 1.f;
}

// =====================================================================
// prep kernels
// =====================================================================
__global__ void prep_x_kernel(const float* __restrict__ x) {
    size_t i = (size_t)blockIdx.x * blockDim.x + threadIdx.x;
    const size_t Ntot = (size_t)T * RPAD * CPAD;
    if (i >= Ntot) return;
    int c = i % CPAD;
    int r = (i / CPAD) % RPAD;
    int t = i / ((size_t)CPAD * RPAD);
    float v = 0.f;
    if (r >= 2 && r < 2 + L && c < CIN)
        v = x[(((size_t)(r - 2)) * T + t) * CIN + c];
    __nv_bfloat16 hi = __float2bfloat16(v);
    __nv_bfloat16 lo = __float2bfloat16(v - __bfloat162float(hi));
    g_xtp_hi[i] = hi;
    g_xtp_lo[i] = lo;
}

__global__ void prep_wb_kernel(const float* __restrict__ Wi,
                               const float* __restrict__ Wh) {
    if (blockIdx.x == 0 && threadIdx.x < 8) g_sync[threadIdx.x] = 0u;
    size_t i = (size_t)blockIdx.x * blockDim.x + threadIdx.x;
    const size_t Ntot = (size_t)(NB + 480) * KPAD;
    if (i >= Ntot) return;
    int k = i % KPAD;
    int n = i / KPAD;
    int tap = k / CPAD, c = k % CPAD;
    float v = 0.f;
    if (n < NB) {
        if (n < J3 && tap < KW && c < CIN)
            v = Wi[((size_t)tap * CIN + c) * J3 + n];
        __nv_bfloat16 hi = __float2bfloat16(v);
        __nv_bfloat16 lo = __float2bfloat16(v - __bfloat162float(hi));
        g_B_hi[(size_t)n * KPAD + k] = hi;
        g_B_lo[(size_t)n * KPAD + k] = lo;
    } else {
        int n2 = n - NB;
        int cg = n2 >> 5, j = n2 & 31;
        if (j < 30 && tap < KW && c < CIN) {
            int gate = j / 10, ch = j - gate * 10;
            v = Wh[((size_t)tap * CIN + c) * J3 + gate * HID + cg * 10 + ch];
        }
        __nv_bfloat16 hi = __float2bfloat16(v);
        __nv_bfloat16 lo = __float2bfloat16(v - __bfloat162float(hi));
        g_Br_hi[(size_t)n2 * KPAD + k] = hi;
        g_Br_lo[(size_t)n2 * KPAD + k] = lo;
    }
}

// =====================================================================
// xi via mma.sync bf16 split, v4: 64x128 block tile, 256 thr, 2-buffer
// cp.async DB, 96KB smem -> 2 blocks/SM co-residency (latency hiding).
// grid (96 t, 8 m, 4 n); warp tile 32x32 (2mw x 4nw) — inner loop
// identical to the R12-proven version.
// Buffer layout (48KB): [A_hi 8K][A_lo 8K][B_hi 16K][B_lo 16K].
// =====================================================================
#define BUFSZ 49152

__global__ __launch_bounds__(256, 1) void xi_mma_kernel(
    const float* __restrict__ bi, float* __restrict__ xi)
{
    char* sm = reinterpret_cast<char*>(smem);
    const uint32_t smb = smem_u32(sm);
    const int tid = threadIdx.x;
    const int lane = tid & 31, wid = tid >> 5;
    const int t = blockIdx.x, mblk = blockIdx.y, nblk = blockIdx.z;

    const int mw = wid & 1, nw = wid >> 1;   // 2 x 4 warps
    const int m0 = mw * 32, n0 = nw * 32;

    int aRow[2], aXor[2];
    const int jA = (lane >> 4) & 1;
    #pragma unroll
    for (int mt = 0; mt < 2; mt++) {
        aRow[mt] = (m0 + mt * 16 + (lane & 15)) * 128;
        aXor[mt] = ((m0 + mt * 16 + (lane & 15)) & 7);
    }
    int bRow[2], bXor[2];
    const int jB = (lane >> 3) & 1;
    #pragma unroll
    for (int np = 0; np < 2; np++) {
        int r = n0 + np * 16 + (lane & 7) + ((lane >> 4) & 1) * 8;
        bRow[np] = r * 128;
        bXor[np] = r & 7;
    }

    const __nv_bfloat16* srcA_hi = g_xtp_hi + ((size_t)t * RPAD + (size_t)mblk * 64) * CPAD;
    const __nv_bfloat16* srcA_lo = g_xtp_lo + ((size_t)t * RPAD + (size_t)mblk * 64) * CPAD;
    const __nv_bfloat16* srcB_hi = g_B_hi + (size_t)nblk * 128 * KPAD;
    const __nv_bfloat16* srcB_lo = g_B_lo + (size_t)nblk * 128 * KPAD;

    float acc[2][4][4];
    #pragma unroll
    for (int mt = 0; mt < 2; mt++)
        #pragma unroll
        for (int nt = 0; nt < 4; nt++)
            #pragma unroll
            for (int k = 0; k < 4; k++) acc[mt][nt][k] = 0.f;

    // per chunk: A 2arr x 64rows x 8segs = 1024; B 2arr x 128rows x 8segs = 2048
    auto stage = [&](int kc, int buf) {
        const uint32_t base = smb + buf * BUFSZ;
        #pragma unroll
        for (int it = 0; it < 12; it++) {
            int u = it * 256 + tid;
            const __nv_bfloat16* src;
            uint32_t dstoff;
            if (u < 1024) {
                int arr = u >> 9;           // 0:A_hi 1:A_lo
                int v = u & 511;
                int row = v >> 3, seg = v & 7;
                src = (arr ? srcA_lo : srcA_hi) + (size_t)row * CPAD + kc * KC + seg * 8;
                dstoff = arr * 8192 + row * 128 + ((seg ^ (row & 7)) << 4);
            } else {
                int v2 = u - 1024;
                int arr = v2 >> 10;         // 0:B_hi 1:B_lo
                int w = v2 & 1023;
                int row = w >> 3, seg = w & 7;
                src = (arr ? srcB_lo : srcB_hi) + (size_t)row * KPAD + kc * KC + seg * 8;
                dstoff = 16384 + arr * 16384 + row * 128 + ((seg ^ (row & 7)) << 4);
            }
            CP_ASYNC16(base + dstoff, src);
        }
    };

    stage(0, 0);
    CP_COMMIT();

    for (int kc = 0; kc < NKC; kc++) {
        const int buf = kc & 1;
        if (kc + 1 < NKC) {
            stage(kc + 1, buf ^ 1);
            CP_COMMIT();
            CP_WAIT1();
        } else {
            CP_WAIT0();
        }
        __syncthreads();

        const uint32_t bA_hi = smb + buf * BUFSZ;
        const uint32_t bA_lo = bA_hi + 8192;
        const uint32_t bB_hi = bA_hi + 16384;
        const uint32_t bB_lo = bA_hi + 32768;

        #pragma unroll
        for (int ks = 0; ks < 4; ks++) {
            uint32_t ah[2][4], al[2][4];
            #pragma unroll
            for (int mt = 0; mt < 2; mt++) {
                uint32_t off = aRow[mt] + (((2 * ks + jA) ^ aXor[mt]) << 4);
                LDSM_X4(ah[mt][0], ah[mt][1], ah[mt][2], ah[mt][3], bA_hi + off);
                LDSM_X4(al[mt][0], al[mt][1], al[mt][2], al[mt][3], bA_lo + off);
            }
            #pragma unroll
            for (int np = 0; np < 2; np++) {
                if (nblk * 128 + n0 + np * 16 >= J3) continue;
                uint32_t off = bRow[np] + (((2 * ks + jB) ^ bXor[np]) << 4);
                uint32_t bh[4], bl[4];
                LDSM_X4(bh[0], bh[1], bh[2], bh[3], bB_hi + off);
                LDSM_X4(bl[0], bl[1], bl[2], bl[3], bB_lo + off);
                #pragma unroll
                for (int mt = 0; mt < 2; mt++) {
                    float* d0 = acc[mt][np * 2];
                    float* d1 = acc[mt][np * 2 + 1];
                    MMA16816(d0, ah[mt][0], ah[mt][1], ah[mt][2], ah[mt][3], bh[0], bh[1]);
                    MMA16816(d0, al[mt][0], al[mt][1], al[mt][2], al[mt][3], bh[0], bh[1]);
                    MMA16816(d0, ah[mt][0], ah[mt][1], ah[mt][2], ah[mt][3], bl[0], bl[1]);
                    MMA16816(d1, ah[mt][0], ah[mt][1], ah[mt][2], ah[mt][3], bh[2], bh[3]);
                    MMA16816(d1, al[mt][0], al[mt][1], al[mt][2], al[mt][3], bh[2], bh[3]);
                    MMA16816(d1, ah[mt][0], ah[mt][1], ah[mt][2], ah[mt][3], bl[2], bl[3]);
                }
            }
        }
        __syncthreads();
    }

    const int g  = lane >> 2;
    const int tq = lane & 3;
    #pragma unroll
    for (int mt = 0; mt < 2; mt++) {
        int r0 = mblk * 64 + m0 + mt * 16 + g;
        int r1 = r0 + 8;
        float* row0 = xi + ((size_t)t * L + r0) * J3P;
        float* row1 = xi + ((size_t)t * L + r1) * J3P;
        #pragma unroll
        for (int nt = 0; nt < 4; nt++) {
            int j0 = nblk * 128 + n0 + nt * 8 + tq * 2;
            if (j0 < J3) {
                float b0 = bi[j0], b1 = bi[j0 + 1];
                float2 v0 = make_float2(acc[mt][nt][0] + b0, acc[mt][nt][1] + b1);
                float2 v1 = make_float2(acc[mt][nt][2] + b0, acc[mt][nt][3] + b1);
                *reinterpret_cast<float2*>(row0 + j0) = v0;
                *reinterpret_cast<float2*>(row1 + j0) = v1;
            }
        }
    }
}

// =====================================================================
// Persistent recurrent MMA kernel — EXACT R15 (best passing: 584us).
// grid (15 cg, 8 mg) = 120 blocks, 512 thr = 16 warps as 4mw x 4kw.
// Full compact halo staged per step from xtp[t-1]; lightweight sync.
// =====================================================================
#define SM_RB_HI 0
#define SM_RB_LO 49152
#define SM_RA    98304
#define HALO_B   20736          // 68*304 = 20672, rounded up to 128
#define SM_RHH   (SM_RA + 2 * HALO_B)          // 139776 (4 x 8192)
#define SM_XI    (SM_RHH + 32768)              // 172544
#define SM_REC_TOTAL (SM_XI + 8192)            // 180736

__global__ __launch_bounds__(512, 1) void rec_mma_kernel(
    const float* __restrict__ xi, float* __restrict__ outp, int layer)
{
    char* sm = reinterpret_cast<char*>(smem);
    const uint32_t smb = smem_u32(sm);
    float* sh_hh0 = reinterpret_cast<float*>(sm + SM_RHH);
    float* sh_hh1 = reinterpret_cast<float*>(sm + SM_RHH + 8192);
    float* sh_hh2 = reinterpret_cast<float*>(sm + SM_RHH + 16384);
    float* sh_hh3 = reinterpret_cast<float*>(sm + SM_RHH + 24576);
    float* sh_xi  = reinterpret_cast<float*>(sm + SM_XI);
    const int tid = threadIdx.x;
    const int lane = tid & 31, wid = tid >> 5;
    const int cg = blockIdx.x, mg = blockIdx.y;
    const int c0 = cg * 10;
    const int l0 = mg * 64;

    const int mw = wid & 3;             // 4 m-warps (16 rows each)
    const int kw = wid >> 2;            // 4 K-split groups (3 kc each)
    const int m0w = mw * 16;
    float* sh_hh_my = (kw == 0) ? sh_hh0 : (kw == 1) ? sh_hh1
                     : (kw == 2) ? sh_hh2 : sh_hh3;

    // A lane offset into compact halo (row stride 304B, k-half select jA)
    const int jA = (lane >> 4) & 1;
    const uint32_t aLane = (uint32_t)(m0w + (lane & 15)) * 304 + jA * 16;
    // B lane addressing (swizzled resident buffer), two n16 groups
    const int bR = (lane & 7) + ((lane >> 4) & 1) * 8;   // rows 0..15
    const int bRowOff0 = bR * 128;
    const int bRowOff1 = (bR + 16) * 128;                // (bR+16)&7 == bR&7
    const int bXor = bR & 7;
    const int jB = (lane >> 3) & 1;

    // ---- zero-init the entire halo region ONCE (t=0 state + K-pad tail) ----
    {
        uint4 z = make_uint4(0, 0, 0, 0);
        for (int u = tid; u < (2 * HALO_B) / 16; u += 512)
            *reinterpret_cast<uint4*>(sm + SM_RA + u * 16) = z;
    }

    // ---- load resident B (weights) once: 2 arr x 12 chunks x 32 rows x 8 segs ----
    for (int u = tid; u < 6144; u += 512) {
        int arr = u / 3072;
        int v = u - arr * 3072;
        int chunk = v >> 8;
        int w = v & 255;
        int row = w >> 3, seg = w & 7;
        const __nv_bfloat16* src =
            (arr ? g_Br_lo : g_Br_hi) + ((size_t)(cg * 32 + row)) * KPAD + chunk * KC + seg * 8;
        uint32_t dst = smb + (arr ? SM_RB_LO : SM_RB_HI)
                     + chunk * 4096 + row * 128 + ((seg ^ (row & 7)) << 4);
        CP_ASYNC16(dst, src);
    }
    CP_COMMIT();
    CP_WAIT0();
    __syncthreads();

    for (int t = 0; t < T; t++) {
        // neighbor sync: tid<3 poll mg-1, mg, mg+1 with acquire loads,
        // then block barrier (contention-free: 3 loads per block).
        if (t > 0) {
            if (tid < 3) {
                int mgn = mg + tid - 1;
                if (mgn < 0) mgn = 0;
                if (mgn > 7) mgn = 7;
                const unsigned tgt = 15u * (unsigned)t;
                while (ld_acquire((const unsigned*)&g_sync[mgn]) < tgt) { }
            }
            __syncthreads();
        }

        // ---- stage compact halo from xtp[t-1] (group 0, gated before MMA) ----
        if (t > 0) {
            const __nv_bfloat16* baseHi = g_xtp_hi + ((size_t)(t - 1) * RPAD + l0) * CPAD;
            const __nv_bfloat16* baseLo = g_xtp_lo + ((size_t)(t - 1) * RPAD + l0) * CPAD;
            for (int u = tid; u < 2584; u += 512) {
                int arr = u >= 1292;
                int v = arr ? u - 1292 : u;
                const __nv_bfloat16* src = (arr ? baseLo : baseHi) + v * 8;
                uint32_t dst = smb + SM_RA + arr * HALO_B + v * 16;
                CP_ASYNC16(dst, src);
            }
            CP_COMMIT();
        }
        // ---- prefetch xi gate slice (group 1, only needed at epilogue) ----
        {
            const float* xibase = xi + ((size_t)t * L + l0) * J3P + c0;
            for (int u = tid; u < 960; u += 512) {
                int lr = u / 15, rem = u - lr * 15;
                int gate = rem / 5, seg = rem - gate * 5;
                const float* src = xibase + (size_t)lr * J3P + gate * HID + seg * 2;
                uint32_t dst = smb + SM_XI + lr * 128 + gate * 40 + seg * 8;
                CP_ASYNC8(dst, src);
            }
            CP_COMMIT();
        }
        if (t > 0) CP_WAIT1();   // halo complete; xi may still be in flight
        __syncthreads();

        float a0[4][4];   // 4 n8-tiles x 4 regs
        #pragma unroll
        for (int nt = 0; nt < 4; nt++)
            #pragma unroll
            for (int k = 0; k < 4; k++) a0[nt][k] = 0.f;

        const uint32_t aHi = smb + SM_RA + aLane;
        const uint32_t aLo = aHi + HALO_B;
        const int kcBeg = kw * 3;

        #pragma unroll
        for (int kc2 = 0; kc2 < 3; kc2++) {
            const int kc = kcBeg + kc2;
            const uint32_t bBh = smb + SM_RB_HI + kc * 4096;
            const uint32_t bBl = smb + SM_RB_LO + kc * 4096;
            #pragma unroll
            for (int ks = 0; ks < 4; ks++) {
                uint32_t aoff = kc * 128 + ks * 32;
                uint32_t ah[4], al[4];
                LDSM_X4(ah[0], ah[1], ah[2], ah[3], aHi + aoff);
                LDSM_X4(al[0], al[1], al[2], al[3], aLo + aoff);
                uint32_t bko = (((2 * ks + jB) ^ bXor) << 4);
                uint32_t bh[8], bl[8];
                LDSM_X4(bh[0], bh[1], bh[2], bh[3], bBh + bRowOff0 + bko);
                LDSM_X4(bh[4], bh[5], bh[6], bh[7], bBh + bRowOff1 + bko);
                LDSM_X4(bl[0], bl[1], bl[2], bl[3], bBl + bRowOff0 + bko);
                LDSM_X4(bl[4], bl[5], bl[6], bl[7], bBl + bRowOff1 + bko);
                #pragma unroll
                for (int j = 0; j < 4; j++) {
                    float* d = a0[j];
                    MMA16816(d, ah[0], ah[1], ah[2], ah[3], bh[2 * j], bh[2 * j + 1]);
                    MMA16816(d, al[0], al[1], al[2], al[3], bh[2 * j], bh[2 * j + 1]);
                    MMA16816(d, ah[0], ah[1], ah[2], ah[3], bl[2 * j], bl[2 * j + 1]);
                }
            }
        }

        // ---- stage hh partials into this K-group's smem buffer ----
        {
            const int g = lane >> 2, tq = lane & 3;
            int r0 = m0w + g;
            int r1 = r0 + 8;
            #pragma unroll
            for (int j = 0; j < 4; j++) {
                int col = j * 8 + tq * 2;
                sh_hh_my[r0 * 32 + col]     = a0[j][0];
                sh_hh_my[r0 * 32 + col + 1] = a0[j][1];
                sh_hh_my[r1 * 32 + col]     = a0[j][2];
                sh_hh_my[r1 * 32 + col + 1] = a0[j][3];
            }
        }
        CP_WAIT0();       // xi slice now resident
        __syncthreads();

        // ---- gate epilogue: 64 rows x 10 channels, all smem-sourced ----
        {
            for (int e = tid; e < 640; e += 512) {
                int lr = e / 10, ch = e - lr * 10;
                int l = l0 + lr, c = c0 + ch;
                int b = lr * 32;
                float hr = sh_hh0[b + ch]      + sh_hh1[b + ch]
                         + sh_hh2[b + ch]      + sh_hh3[b + ch];
                float hz = sh_hh0[b + 10 + ch] + sh_hh1[b + 10 + ch]
                         + sh_hh2[b + 10 + ch] + sh_hh3[b + 10 + ch];
                float hn = sh_hh0[b + 20 + ch] + sh_hh1[b + 20 + ch]
                         + sh_hh2[b + 20 + ch] + sh_hh3[b + 20 + ch];
                const float* qx = sh_xi + lr * 32;
                float xr = qx[ch], xz = qx[10 + ch], xn = qx[20 + ch];
                // h_prev reconstructed from the staged halo (hi+lo)
                uint32_t hoff = (uint32_t)(lr + 2) * 304 + 2u * (uint32_t)c;
                float hpv =
                    __bfloat162float(*reinterpret_cast<__nv_bfloat16*>(sm + SM_RA + hoff)) +
                    __bfloat162float(*reinterpret_cast<__nv_bfloat16*>(sm + SM_RA + HALO_B + hoff));
                float r = sigf(xr + hr);
                float z = sigf(xz + hz);
                float n = tanhfast(xn + r * hn);
                float hnew = n + z * (hpv - n);

                __nv_bfloat16 hi = __float2bfloat16(hnew);
                __nv_bfloat16 lo = __float2bfloat16(hnew - __bfloat162float(hi));
                size_t xidx = ((size_t)t * RPAD + (l + 2)) * CPAD + c;
                g_xtp_hi[xidx] = hi;
                g_xtp_lo[xidx] = lo;
                if (layer == 1)
                    outp[((size_t)l * T + t) * HID + c] = hnew;
            }
        }

        // signal completion of step t: block barrier orders all threads'
        // stores before tid0's release-reduction.
        __syncthreads();
        if (tid == 0) signal_release((unsigned*)&g_sync[mg]);
    }
}

// =====================================================================
extern "C" void kernel_launch(void* const* d_in, const int* in_sizes, int n_in,
                              void* d_out, int out_size)
{
    (void)in_sizes; (void)n_in; (void)out_size;
    const float* xs  = (const float*)d_in[0];
    const float* Wi0 = (const float*)d_in[1];
    const float* bi0 = (const float*)d_in[2];
    const float* Wh0 = (const float*)d_in[3];
    const float* Wi1 = (const float*)d_in[4];
    const float* bi1 = (const float*)d_in[5];
    const float* Wh1 = (const float*)d_in[6];
    float* out = (float*)d_out;

    float* xi;
    cudaGetSymbolAddress((void**)&xi, g_xi);

    const size_t smem_mma = 2 * BUFSZ;   // 96 KB -> 2 blocks/SM
    static int attr_done = 0;
    if (!attr_done) {
        cudaFuncSetAttribute(xi_mma_kernel, cudaFuncAttributeMaxDynamicSharedMemorySize, (int)smem_mma);
        cudaFuncSetAttribute(rec_mma_kernel, cudaFuncAttributeMaxDynamicSharedMemorySize, SM_REC_TOTAL);
        attr_done = 1;
    }

    const size_t n_prep_x = (size_t)T * RPAD * CPAD;
    const int    gx = (int)((n_prep_x + 255) / 256);
    const size_t n_prep_wb = (size_t)(NB + 480) * KPAD;
    const int    gwb = (int)((n_prep_wb + 255) / 256);
    const dim3 grid_mma(T, 8, 4);
    const dim3 grid_rec(15, 8);

    for (int layer = 0; layer < 2; layer++) {
        const float* Wi = layer ? Wi1 : Wi0;
        const float* bi = layer ? bi1 : bi0;
        const float* Wh = layer ? Wh1 : Wh0;

        if (layer == 0) prep_x_kernel<<<gx, 256>>>(xs);
        prep_wb_kernel<<<gwb, 256>>>(Wi, Wh);
        xi_mma_kernel<<<grid_mma, 256, smem_mma>>>(bi, xi);
        rec_mma_kernel<<<grid_rec, 512, SM_REC_TOTAL>>>(xi, out, layer);
    }
}